// round 9
// baseline (speedup 1.0000x reference)
#include <cuda_runtime.h>

#define Bn 32
#define Tn 65536
#define TILE 2048
#define NT 32              /* tiles per row (front-end) */
#define SEGCAP (Tn + 2)
#define BTH 256
#define SPT 16             /* samples per thread in fused scan */
#define CHUNKN (BTH * SPT) /* 4096 samples per scan block */
#define NCHUNK 16          /* chunks per row = Tn/CHUNKN */
#define NBLK (Bn * NCHUNK) /* 512 — single wave at 4 blocks/SM */
#define LAG 256            /* staged history for comb (max lag ~202) */
#define WIN (LAG + CHUNKN)
#define SWSZ (WIN + (WIN >> 5) + 4)

// ---------------- scratch (device globals) ----------------
static __device__ int    g_tO[Bn * NT];
static __device__ float4 g_tP[Bn * NT];
static __device__ int    g_nOn[Bn];
static __device__ unsigned short g_segids[Bn * Tn];  // 4 MB
static __device__ int    g_S[Bn * SEGCAP];
static __device__ float4 g_Bnd[Bn * SEGCAP];
static __device__ float4 g_segA[Bn * SEGCAP];        // m00, m10, v1, v2
static __device__ float2 g_segB[Bn * SEGCAP];        // b0, mu
static __device__ float  g_xd[Bn * Tn];              // 8 MB
static __device__ float4 g_chunkM[NBLK];
static __device__ float2 g_chunkC[NBLK];
static __device__ int    g_flag[NBLK];

#define MIN_W_F     0.007853981633974483f
#define LOG2_400_F  8.643856189774724f
#define LOG2_20_F   4.321928094887363f

__device__ __forceinline__ float fast_sigmoid(float v) {
    return __fdividef(1.0f, 1.0f + __expf(-v));
}
__device__ __forceinline__ int SW(int j) { return j + (j >> 5); }

// N = L after E  (2x2 affine compose)
#define COMPOSE(E00,E01,E10,E11,Ec1,Ec2, L00,L01,L10,L11,Lc1,Lc2, \
                N00,N01,N10,N11,Nc1,Nc2)                          \
    do {                                                          \
        N00 = fmaf(L00, E00, L01 * E10);                          \
        N01 = fmaf(L00, E01, L01 * E11);                          \
        N10 = fmaf(L10, E00, L11 * E10);                          \
        N11 = fmaf(L10, E01, L11 * E11);                          \
        Nc1 = fmaf(L00, Ec1, fmaf(L01, Ec2, Lc1));                \
        Nc2 = fmaf(L10, Ec1, fmaf(L10 * 0.f + L11, Ec2, Lc2));    \
    } while (0)

// NOTE: the L10*0 term above would be a bug; use clean version:
#undef COMPOSE
#define COMPOSE(E00,E01,E10,E11,Ec1,Ec2, L00,L01,L10,L11,Lc1,Lc2, \
                N00,N01,N10,N11,Nc1,Nc2)                          \
    do {                                                          \
        N00 = fmaf(L00, E00, L01 * E10);                          \
        N01 = fmaf(L00, E01, L01 * E11);                          \
        N10 = fmaf(L10, E00, L11 * E10);                          \
        N11 = fmaf(L10, E01, L11 * E11);                          \
        Nc1 = fmaf(L00, Ec1, fmaf(L01, Ec2, Lc1));                \
        Nc2 = fmaf(L10, Ec1, fmaf(L11, Ec2, Lc2));                \
    } while (0)

// =====================================================================
// K1: per-tile totals (coalesced, vectorized)
// =====================================================================
__global__ void __launch_bounds__(256) k_tile(const int4* __restrict__ onsets4,
                                              const float4* __restrict__ params) {
    int blk = blockIdx.x;
    int row = blk >> 5, tile = blk & (NT - 1);
    long base = (long)row * Tn + (long)tile * TILE;
    int tid = threadIdx.x;

    int o = 0;
    float4 ps = make_float4(0.f, 0.f, 0.f, 0.f);
#pragma unroll
    for (int k = 0; k < 2; k++) {
        int4 v = onsets4[(base >> 2) + k * 256 + tid];
        o += v.x + v.y + v.z + v.w;
    }
#pragma unroll
    for (int r = 0; r < 8; r++) {
        float4 p = params[base + r * 256 + tid];
        ps.x += p.x; ps.y += p.y; ps.z += p.z; ps.w += p.w;
    }
#pragma unroll
    for (int off = 16; off; off >>= 1) {
        o    += __shfl_down_sync(~0u, o, off);
        ps.x += __shfl_down_sync(~0u, ps.x, off);
        ps.y += __shfl_down_sync(~0u, ps.y, off);
        ps.z += __shfl_down_sync(~0u, ps.z, off);
        ps.w += __shfl_down_sync(~0u, ps.w, off);
    }
    __shared__ int    so[8];
    __shared__ float4 sp[8];
    int lane = tid & 31, wid = tid >> 5;
    if (lane == 0) { so[wid] = o; sp[wid] = ps; }
    __syncthreads();
    if (tid == 0) {
        int ot = 0; float4 pt = make_float4(0.f, 0.f, 0.f, 0.f);
#pragma unroll
        for (int w = 0; w < 8; w++) {
            ot += so[w];
            pt.x += sp[w].x; pt.y += sp[w].y; pt.z += sp[w].z; pt.w += sp[w].w;
        }
        g_tO[blk] = ot;
        g_tP[blk] = pt;
    }
}

// =====================================================================
// K2: segids + boundary scatter (thread-sequential + shfl scans)
// =====================================================================
__global__ void __launch_bounds__(256) k_ids(const int4* __restrict__ onsets4,
                                             const float4* __restrict__ params) {
    int blk = blockIdx.x;
    int row = blk >> 5, tile = blk & (NT - 1);
    long rowbase = (long)row * Tn;
    long base = rowbase + (long)tile * TILE;
    int tid = threadIdx.x, lane = tid & 31, wid = tid >> 5;
    int rowoff = row * SEGCAP;

    __shared__ int    waggO[8];
    __shared__ float4 waggP[8];
    __shared__ int    s_carO;
    __shared__ float4 s_carP;

    if (wid == 0) {
        int co = 0;
        float4 cp = make_float4(0.f, 0.f, 0.f, 0.f);
        if (lane < tile) {
            int pb = (row << 5) + lane;
            co = g_tO[pb];
            cp = g_tP[pb];
        }
#pragma unroll
        for (int off = 16; off; off >>= 1) {
            co   += __shfl_down_sync(~0u, co, off);
            cp.x += __shfl_down_sync(~0u, cp.x, off);
            cp.y += __shfl_down_sync(~0u, cp.y, off);
            cp.z += __shfl_down_sync(~0u, cp.z, off);
            cp.w += __shfl_down_sync(~0u, cp.w, off);
        }
        if (lane == 0) { s_carO = co; s_carP = cp; }
    }

    long ebase = base + (long)tid * 8;
    int4 oa = onsets4[ebase >> 2];
    int4 ob = onsets4[(ebase >> 2) + 1];
    int ol[8] = { oa.x, oa.y, oa.z, oa.w, ob.x, ob.y, ob.z, ob.w };
    float4 pl[8];
#pragma unroll
    for (int i = 0; i < 8; i++) pl[i] = params[ebase + i];

    int totO = 0;
    float4 totP = make_float4(0.f, 0.f, 0.f, 0.f);
#pragma unroll
    for (int i = 0; i < 8; i++) {
        totO += ol[i];
        totP.x += pl[i].x; totP.y += pl[i].y; totP.z += pl[i].z; totP.w += pl[i].w;
    }

    int inO = totO;
    float4 inP = totP;
#pragma unroll
    for (int off = 1; off < 32; off <<= 1) {
        int   eo = __shfl_up_sync(~0u, inO, off);
        float a = __shfl_up_sync(~0u, inP.x, off);
        float b = __shfl_up_sync(~0u, inP.y, off);
        float c = __shfl_up_sync(~0u, inP.z, off);
        float d = __shfl_up_sync(~0u, inP.w, off);
        if (lane >= off) { inO += eo; inP.x += a; inP.y += b; inP.z += c; inP.w += d; }
    }
    int exO = __shfl_up_sync(~0u, inO, 1);
    float4 exP;
    exP.x = __shfl_up_sync(~0u, inP.x, 1);
    exP.y = __shfl_up_sync(~0u, inP.y, 1);
    exP.z = __shfl_up_sync(~0u, inP.z, 1);
    exP.w = __shfl_up_sync(~0u, inP.w, 1);
    if (lane == 0) { exO = 0; exP = make_float4(0.f, 0.f, 0.f, 0.f); }
    if (lane == 31) { waggO[wid] = inO; waggP[wid] = inP; }
    __syncthreads();

    int weO = 0;
    float4 weP = make_float4(0.f, 0.f, 0.f, 0.f);
#pragma unroll
    for (int w = 0; w < 8; w++) {
        if (w < wid) {
            weO += waggO[w];
            weP.x += waggP[w].x; weP.y += waggP[w].y;
            weP.z += waggP[w].z; weP.w += waggP[w].w;
        }
    }

    int carO = s_carO;
    float4 carP = s_carP;
    if (tid == 0 && tile == 0) {
        g_S[rowoff] = 0;
        g_Bnd[rowoff] = make_float4(0.f, 0.f, 0.f, 0.f);
    }

    int id = carO + weO + exO;
    float4 pex = make_float4(carP.x + weP.x + exP.x, carP.y + weP.y + exP.y,
                             carP.z + weP.z + exP.z, carP.w + weP.w + exP.w);
#pragma unroll
    for (int i = 0; i < 8; i++) {
        id += ol[i];
        g_segids[ebase + i] = (unsigned short)id;
        if (ol[i]) {
            g_S[rowoff + id] = (int)(ebase + i - rowbase);
            g_Bnd[rowoff + id] = pex;
        }
        pex.x += pl[i].x; pex.y += pl[i].y; pex.z += pl[i].z; pex.w += pl[i].w;
    }

    if (tid == 255 && tile == NT - 1) {
        g_nOn[row] = id;
        g_S[rowoff + id + 1]   = Tn;
        g_Bnd[rowoff + id + 1] = pex;
    }
}

// =====================================================================
// K3: xd = x * dist (vectorized); blocks 0..Bn-1 also build tables
// =====================================================================
__global__ void __launch_bounds__(256) k_xd(const float4* __restrict__ x4) {
    int v = blockIdx.x * 256 + threadIdx.x;
    int idx = v << 2;
    int row = idx >> 16;
    int rowoff = row * SEGCAP;
    uint2 sv = *(const uint2*)&g_segids[idx];
    int id0 = sv.x & 0xffff, id3 = sv.y >> 16;
    float4 xv = x4[v];
    float4 ov;
    if (id0 == id3) {
        int ro = rowoff + id0;
        float num = g_Bnd[ro + 1].x - g_Bnd[ro].x;
        float den = (float)(g_S[ro + 1] - g_S[ro]);
        float a = num * __fdividef(1.f, fmaxf(den, 1.f));
        float dist = 0.1f * exp2f(fast_sigmoid(a) * LOG2_20_F);
        ov = make_float4(xv.x * dist, xv.y * dist, xv.z * dist, xv.w * dist);
    } else {
        int ids[4] = { (int)(sv.x & 0xffff), (int)(sv.x >> 16),
                       (int)(sv.y & 0xffff), (int)(sv.y >> 16) };
        float* o = &ov.x;
        const float* xi = &xv.x;
#pragma unroll
        for (int i = 0; i < 4; i++) {
            int ro = rowoff + ids[i];
            float num = g_Bnd[ro + 1].x - g_Bnd[ro].x;
            float den = (float)(g_S[ro + 1] - g_S[ro]);
            float a = num * __fdividef(1.f, fmaxf(den, 1.f));
            o[i] = xi[i] * (0.1f * exp2f(fast_sigmoid(a) * LOG2_20_F));
        }
    }
    *(float4*)&g_xd[idx] = ov;

    if (blockIdx.x < Bn) {
        int srow = blockIdx.x;
        int ro0 = srow * SEGCAP;
        int nOn = g_nOn[srow];
        for (int s = threadIdx.x; s <= nOn; s += 256) {
            int r2 = ro0 + s;
            float4 B0 = g_Bnd[r2], B1 = g_Bnd[r2 + 1];
            float d2 = (float)(g_S[r2 + 1] - g_S[r2]);
            float invc = __fdividef(1.f, fmaxf(d2, 1.f));
            float wmod = fast_sigmoid((B1.y - B0.y) * invc);
            float qmod = fast_sigmoid((B1.z - B0.z) * invc);
            float mu   = fast_sigmoid((B1.w - B0.w) * invc);

            float w = MIN_W_F * exp2f(wmod * LOG2_400_F);
            float q = 0.1f * exp2f(qmod * LOG2_20_F);
            float sh, ch;
            __sincosf(0.5f * w, &sh, &ch);
            float omc = 2.f * sh * sh;
            float cw = 1.f - omc;
            float sw = 2.f * sh * ch;
            float alpha = __fdividef(sw, 2.f * q);
            float inva0 = __fdividef(1.f, 1.f + alpha);
            float b0 = 0.5f * omc * inva0;
            float b1c = omc * inva0;
            float a1 = -2.f * cw * inva0;
            float a2 = (1.f - alpha) * inva0;

            g_segA[r2] = make_float4(-a1, -a2, b1c - a1 * b0, b0 - a2 * b0);
            g_segB[r2] = make_float2(b0, mu);
        }
    }
}

// =====================================================================
// K4 (fused): comb + compose + block scan + SINGLE-WAVE spin lookback
//             + replay + output.  512 blocks, 4/SM guaranteed resident.
// =====================================================================
#define IDAT(i) ((int)(((i) & 1) ? (idw[(i) >> 1] >> 16) : (idw[(i) >> 1] & 0xffffu)))

__global__ void __launch_bounds__(BTH, 4) k_scan(const float* __restrict__ f0,
                                                 float* __restrict__ out) {
    __shared__ float sxd[SWSZ];        // staged xd window; reused for xc
    __shared__ float wagg[8][6];
    __shared__ float2 s_cin;

    int tid = threadIdx.x, lane = tid & 31, wid = tid >> 5;
    int blk = blockIdx.x;
    int base = blk * CHUNKN;
    int t0 = base & (Tn - 1);
    int rowoff = (base >> 16) * SEGCAP;
    int lbase = tid * SPT;
    int gbase = base + lbase;

    // ---- stage xd window [base-LAG, base+CHUNKN) ----
    for (int k = tid; k < WIN / 4; k += BTH) {
        int off = k << 2;
        float4 v = make_float4(0.f, 0.f, 0.f, 0.f);
        if (t0 + off >= LAG) v = *(const float4*)&g_xd[base - LAG + off];
        sxd[SW(off)]     = v.x;
        sxd[SW(off + 1)] = v.y;
        sxd[SW(off + 2)] = v.z;
        sxd[SW(off + 3)] = v.w;
    }
    __syncthreads();

    // ---- segment ids (packed), uniformity fast path ----
    unsigned idw[8];
    {
        uint4 a = *(const uint4*)&g_segids[gbase];
        uint4 b = *(const uint4*)&g_segids[gbase + 8];
        idw[0] = a.x; idw[1] = a.y; idw[2] = a.z; idw[3] = a.w;
        idw[4] = b.x; idw[5] = b.y; idw[6] = b.z; idw[7] = b.w;
    }
    bool uni = (IDAT(0) == IDAT(15));
    float4 T = g_segA[rowoff + IDAT(0)];
    float2 Bc = g_segB[rowoff + IDAT(0)];

    // ---- comb + thread compose over SPT steps ----
    float xc[SPT];
    float A00 = 1.f, A01 = 0.f, A10 = 0.f, A11 = 1.f, Ac1 = 0.f, Ac2 = 0.f;
#pragma unroll
    for (int g = 0; g < SPT / 4; g++) {
        float4 f4 = *(const float4*)&f0[gbase + g * 4];
        const float fv[4] = { f4.x, f4.y, f4.z, f4.w };
#pragma unroll
        for (int j = 0; j < 4; j++) {
            int i = g * 4 + j;
            if (!uni && i) {
                int sid = IDAT(i);
                T = g_segA[rowoff + sid];
                Bc = g_segB[rowoff + sid];
            }
            float p = fv[j] * Bc.y;
            int zi = (int)p;                  // p > 0 always
            float alfa = p - (float)zi;
            int li = LAG + lbase + i;
            float x1 = sxd[SW(li - zi - 1)];
            float x2 = sxd[SW(li - zi - 2)];
            float v = sxd[SW(li)] - (1.f - alfa) * x1 - alfa * x2;
            xc[i] = v;
            // compose step [[T.x,1],[T.y,0]], c = (T.z*v, T.w*v)
            float n00 = fmaf(T.x, A00, A10);
            float n01 = fmaf(T.x, A01, A11);
            float n10 = T.y * A00;
            float n11 = T.y * A01;
            float t1  = fmaf(T.x, Ac1, Ac2) + T.z * v;
            float t2  = fmaf(T.y, Ac1, T.w * v);
            A00 = n00; A01 = n01; A10 = n10; A11 = n11; Ac1 = t1; Ac2 = t2;
        }
    }
    __syncthreads();   // all comb reads done — window is dead
    // overwrite own region with xc (frees registers conceptually after stores)
#pragma unroll
    for (int i = 0; i < SPT; i++) sxd[SW(LAG + lbase + i)] = xc[i];

    // ---- warp inclusive KS of thread transforms ----
#pragma unroll
    for (int off = 1; off < 32; off <<= 1) {
        float E00 = __shfl_up_sync(~0u, A00, off);
        float E01 = __shfl_up_sync(~0u, A01, off);
        float E10 = __shfl_up_sync(~0u, A10, off);
        float E11 = __shfl_up_sync(~0u, A11, off);
        float Ec1 = __shfl_up_sync(~0u, Ac1, off);
        float Ec2 = __shfl_up_sync(~0u, Ac2, off);
        if (lane >= off) {
            float N00, N01, N10, N11, Nc1, Nc2;
            COMPOSE(E00,E01,E10,E11,Ec1,Ec2, A00,A01,A10,A11,Ac1,Ac2,
                    N00,N01,N10,N11,Nc1,Nc2);
            A00 = N00; A01 = N01; A10 = N10; A11 = N11; Ac1 = Nc1; Ac2 = Nc2;
        }
    }
    float X00 = __shfl_up_sync(~0u, A00, 1);
    float X01 = __shfl_up_sync(~0u, A01, 1);
    float X10 = __shfl_up_sync(~0u, A10, 1);
    float X11 = __shfl_up_sync(~0u, A11, 1);
    float Xc1 = __shfl_up_sync(~0u, Ac1, 1);
    float Xc2 = __shfl_up_sync(~0u, Ac2, 1);
    if (lane == 0) { X00 = 1.f; X01 = 0.f; X10 = 0.f; X11 = 1.f; Xc1 = 0.f; Xc2 = 0.f; }
    if (lane == 31) {
        wagg[wid][0] = A00; wagg[wid][1] = A01; wagg[wid][2] = A10;
        wagg[wid][3] = A11; wagg[wid][4] = Ac1; wagg[wid][5] = Ac2;
    }
    __syncthreads();

    // ---- warp 0: block aggregate -> publish; then spin lookback ----
    if (wid == 0) {
        if (lane < 8) {
            float W00 = wagg[lane][0], W01 = wagg[lane][1], W10 = wagg[lane][2];
            float W11 = wagg[lane][3], Wc1 = wagg[lane][4], Wc2 = wagg[lane][5];
#pragma unroll
            for (int off = 1; off < 8; off <<= 1) {
                float L00 = __shfl_down_sync(0xffu, W00, off);
                float L01 = __shfl_down_sync(0xffu, W01, off);
                float L10 = __shfl_down_sync(0xffu, W10, off);
                float L11 = __shfl_down_sync(0xffu, W11, off);
                float Lc1 = __shfl_down_sync(0xffu, Wc1, off);
                float Lc2 = __shfl_down_sync(0xffu, Wc2, off);
                float N00, N01, N10, N11, Nc1, Nc2;
                COMPOSE(W00,W01,W10,W11,Wc1,Wc2, L00,L01,L10,L11,Lc1,Lc2,
                        N00,N01,N10,N11,Nc1,Nc2);
                W00 = N00; W01 = N01; W10 = N10; W11 = N11; Wc1 = Nc1; Wc2 = Nc2;
            }
            if (lane == 0) {
                g_chunkM[blk] = make_float4(W00, W01, W10, W11);
                g_chunkC[blk] = make_float2(Wc1, Wc2);
                __threadfence();
                *(volatile int*)&g_flag[blk] = 1;
            }
        }
        // spin lookback over same-row predecessors (all co-resident)
        int chunk = blk & (NCHUNK - 1);
        int rowBlk = blk - chunk;
        float T00 = 1.f, T01 = 0.f, T10 = 0.f, T11 = 1.f, Tc1 = 0.f, Tc2 = 0.f;
        if (lane < chunk) {
            int pb = rowBlk + lane;
            while (*(volatile int*)&g_flag[pb] == 0) {}
            __threadfence();
            float4 M = g_chunkM[pb];
            float2 C = g_chunkC[pb];
            T00 = M.x; T01 = M.y; T10 = M.z; T11 = M.w; Tc1 = C.x; Tc2 = C.y;
        }
#pragma unroll
        for (int off = 1; off < 16; off <<= 1) {
            float E00 = __shfl_up_sync(~0u, T00, off);
            float E01 = __shfl_up_sync(~0u, T01, off);
            float E10 = __shfl_up_sync(~0u, T10, off);
            float E11 = __shfl_up_sync(~0u, T11, off);
            float Ec1 = __shfl_up_sync(~0u, Tc1, off);
            float Ec2 = __shfl_up_sync(~0u, Tc2, off);
            if (lane >= off) {
                float N00, N01, N10, N11, Nc1, Nc2;
                COMPOSE(E00,E01,E10,E11,Ec1,Ec2, T00,T01,T10,T11,Tc1,Tc2,
                        N00,N01,N10,N11,Nc1,Nc2);
                T00 = N00; T01 = N01; T10 = N10; T11 = N11; Tc1 = Nc1; Tc2 = Nc2;
            }
        }
        float i1 = 0.f, i2 = 0.f;
        if (chunk > 0) {
            i1 = __shfl_sync(~0u, Tc1, chunk - 1);
            i2 = __shfl_sync(~0u, Tc2, chunk - 1);
        }
        if (lane == 0) s_cin = make_float2(i1, i2);
    }
    __syncthreads();

    // ---- incoming state: cin -> warp-exclusive -> lane-exclusive ----
    float2 cin = s_cin;
    float s1 = cin.x, s2 = cin.y;
#pragma unroll
    for (int w = 0; w < 8; w++) {
        if (w < wid) {
            float n1 = fmaf(wagg[w][0], s1, fmaf(wagg[w][1], s2, wagg[w][4]));
            float n2 = fmaf(wagg[w][2], s1, fmaf(wagg[w][3], s2, wagg[w][5]));
            s1 = n1; s2 = n2;
        }
    }
    float st1 = fmaf(X00, s1, fmaf(X01, s2, Xc1));
    float st2 = fmaf(X10, s1, fmaf(X11, s2, Xc2));

    // ---- replay from smem xc + table ----
    float4 T2 = g_segA[rowoff + IDAT(0)];
    float2 B2 = g_segB[rowoff + IDAT(0)];
#pragma unroll
    for (int g = 0; g < SPT / 4; g++) {
        float4 o4;
        float* op = &o4.x;
#pragma unroll
        for (int j = 0; j < 4; j++) {
            int i = g * 4 + j;
            if (!uni && i) {
                int sid = IDAT(i);
                T2 = g_segA[rowoff + sid];
                B2 = g_segB[rowoff + sid];
            }
            float v = sxd[SW(LAG + lbase + i)];
            op[j] = fmaf(B2.x, v, st1);
            float n1 = fmaf(T2.x, st1, st2) + T2.z * v;
            float n2 = fmaf(T2.y, st1, T2.w * v);
            st1 = n1; st2 = n2;
        }
        *(float4*)&out[gbase + g * 4] = o4;
    }
}

// =====================================================================
extern "C" void kernel_launch(void* const* d_in, const int* in_sizes, int n_in,
                              void* d_out, int out_size) {
    const float* f0     = (const float*)d_in[0];
    const float* x      = (const float*)d_in[1];
    const float* params = (const float*)d_in[2];
    const int*   onsets = (const int*)d_in[3];
    float* out = (float*)d_out;

    void* pF = nullptr;
    cudaGetSymbolAddress(&pF, g_flag);
    cudaMemsetAsync(pF, 0, sizeof(int) * NBLK);

    k_tile<<<Bn * NT, 256>>>((const int4*)onsets, (const float4*)params);
    k_ids<<<Bn * NT, 256>>>((const int4*)onsets, (const float4*)params);
    k_xd<<<(Bn * Tn / 4) / 256, 256>>>((const float4*)x);
    k_scan<<<NBLK, BTH>>>(f0, out);
}

// round 10
// speedup vs baseline: 1.1737x; 1.1737x over previous
#include <cuda_runtime.h>

#define Bn 32
#define Tn 65536
#define TILE 2048
#define NT 32              /* tiles per row */
#define SEGCAP (Tn + 2)
#define NCHUNK 32
#define BTH 256
#define SPT 8              /* samples per thread in scan kernels */
#define LAG 256            /* staged history for comb (max lag ~202) */
#define CHUNKN (BTH * SPT) /* 2048 samples per scan block */
#define WIN (LAG + CHUNKN)
#define SWSZ (WIN + (WIN >> 5) + 4)

// ---------------- scratch (device globals) ----------------
static __device__ int    g_tO[Bn * NT];
static __device__ float4 g_tP[Bn * NT];
static __device__ int    g_nOn[Bn];
static __device__ unsigned short g_segids[Bn * Tn];  // 4 MB
static __device__ int    g_S[Bn * SEGCAP];
static __device__ float4 g_Bnd[Bn * SEGCAP];
static __device__ float4 g_segA[Bn * SEGCAP];        // m00, m10, v1, v2
static __device__ float2 g_segB[Bn * SEGCAP];        // b0, mu
static __device__ float  g_segD[Bn * SEGCAP];        // dist
static __device__ float  g_xc[Bn * Tn];              // 8 MB (comb output)
static __device__ float4 g_chunkM[Bn * NCHUNK];
static __device__ float2 g_chunkC[Bn * NCHUNK];

#define MIN_W_F     0.007853981633974483f
#define LOG2_400_F  8.643856189774724f
#define LOG2_20_F   4.321928094887363f

__device__ __forceinline__ float fast_sigmoid(float v) {
    return __fdividef(1.0f, 1.0f + __expf(-v));
}
__device__ __forceinline__ int SW(int j) { return j + (j >> 5); }

// N = L after E  (2x2 affine compose)
#define COMPOSE(E00,E01,E10,E11,Ec1,Ec2, L00,L01,L10,L11,Lc1,Lc2, \
                N00,N01,N10,N11,Nc1,Nc2)                          \
    do {                                                          \
        N00 = fmaf(L00, E00, L01 * E10);                          \
        N01 = fmaf(L00, E01, L01 * E11);                          \
        N10 = fmaf(L10, E00, L11 * E10);                          \
        N11 = fmaf(L10, E01, L11 * E11);                          \
        Nc1 = fmaf(L00, Ec1, fmaf(L01, Ec2, Lc1));                \
        Nc2 = fmaf(L10, Ec1, fmaf(L11, Ec2, Lc2));                \
    } while (0)

// =====================================================================
// K1: per-tile totals (coalesced, vectorized)
// =====================================================================
__global__ void __launch_bounds__(256) k_tile(const int4* __restrict__ onsets4,
                                              const float4* __restrict__ params) {
    int blk = blockIdx.x;
    int row = blk >> 5, tile = blk & (NT - 1);
    long base = (long)row * Tn + (long)tile * TILE;
    int tid = threadIdx.x;

    int o = 0;
    float4 ps = make_float4(0.f, 0.f, 0.f, 0.f);
#pragma unroll
    for (int k = 0; k < 2; k++) {
        int4 v = onsets4[(base >> 2) + k * 256 + tid];
        o += v.x + v.y + v.z + v.w;
    }
#pragma unroll
    for (int r = 0; r < 8; r++) {
        float4 p = params[base + r * 256 + tid];
        ps.x += p.x; ps.y += p.y; ps.z += p.z; ps.w += p.w;
    }
#pragma unroll
    for (int off = 16; off; off >>= 1) {
        o    += __shfl_down_sync(~0u, o, off);
        ps.x += __shfl_down_sync(~0u, ps.x, off);
        ps.y += __shfl_down_sync(~0u, ps.y, off);
        ps.z += __shfl_down_sync(~0u, ps.z, off);
        ps.w += __shfl_down_sync(~0u, ps.w, off);
    }
    __shared__ int    so[8];
    __shared__ float4 sp[8];
    int lane = tid & 31, wid = tid >> 5;
    if (lane == 0) { so[wid] = o; sp[wid] = ps; }
    __syncthreads();
    if (tid == 0) {
        int ot = 0; float4 pt = make_float4(0.f, 0.f, 0.f, 0.f);
#pragma unroll
        for (int w = 0; w < 8; w++) {
            ot += so[w];
            pt.x += sp[w].x; pt.y += sp[w].y; pt.z += sp[w].z; pt.w += sp[w].w;
        }
        g_tO[blk] = ot;
        g_tP[blk] = pt;
    }
}

// =====================================================================
// K2: segids + boundary scatter (thread-sequential + shfl scans)
// =====================================================================
__global__ void __launch_bounds__(256) k_ids(const int4* __restrict__ onsets4,
                                             const float4* __restrict__ params) {
    int blk = blockIdx.x;
    int row = blk >> 5, tile = blk & (NT - 1);
    long rowbase = (long)row * Tn;
    long base = rowbase + (long)tile * TILE;
    int tid = threadIdx.x, lane = tid & 31, wid = tid >> 5;
    int rowoff = row * SEGCAP;

    __shared__ int    waggO[8];
    __shared__ float4 waggP[8];
    __shared__ int    s_carO;
    __shared__ float4 s_carP;

    if (wid == 0) {
        int co = 0;
        float4 cp = make_float4(0.f, 0.f, 0.f, 0.f);
        if (lane < tile) {
            int pb = (row << 5) + lane;
            co = g_tO[pb];
            cp = g_tP[pb];
        }
#pragma unroll
        for (int off = 16; off; off >>= 1) {
            co   += __shfl_down_sync(~0u, co, off);
            cp.x += __shfl_down_sync(~0u, cp.x, off);
            cp.y += __shfl_down_sync(~0u, cp.y, off);
            cp.z += __shfl_down_sync(~0u, cp.z, off);
            cp.w += __shfl_down_sync(~0u, cp.w, off);
        }
        if (lane == 0) { s_carO = co; s_carP = cp; }
    }

    long ebase = base + (long)tid * 8;
    int4 oa = onsets4[ebase >> 2];
    int4 ob = onsets4[(ebase >> 2) + 1];
    int ol[8] = { oa.x, oa.y, oa.z, oa.w, ob.x, ob.y, ob.z, ob.w };
    float4 pl[8];
#pragma unroll
    for (int i = 0; i < 8; i++) pl[i] = params[ebase + i];

    int totO = 0;
    float4 totP = make_float4(0.f, 0.f, 0.f, 0.f);
#pragma unroll
    for (int i = 0; i < 8; i++) {
        totO += ol[i];
        totP.x += pl[i].x; totP.y += pl[i].y; totP.z += pl[i].z; totP.w += pl[i].w;
    }

    int inO = totO;
    float4 inP = totP;
#pragma unroll
    for (int off = 1; off < 32; off <<= 1) {
        int   eo = __shfl_up_sync(~0u, inO, off);
        float a = __shfl_up_sync(~0u, inP.x, off);
        float b = __shfl_up_sync(~0u, inP.y, off);
        float c = __shfl_up_sync(~0u, inP.z, off);
        float d = __shfl_up_sync(~0u, inP.w, off);
        if (lane >= off) { inO += eo; inP.x += a; inP.y += b; inP.z += c; inP.w += d; }
    }
    int exO = __shfl_up_sync(~0u, inO, 1);
    float4 exP;
    exP.x = __shfl_up_sync(~0u, inP.x, 1);
    exP.y = __shfl_up_sync(~0u, inP.y, 1);
    exP.z = __shfl_up_sync(~0u, inP.z, 1);
    exP.w = __shfl_up_sync(~0u, inP.w, 1);
    if (lane == 0) { exO = 0; exP = make_float4(0.f, 0.f, 0.f, 0.f); }
    if (lane == 31) { waggO[wid] = inO; waggP[wid] = inP; }
    __syncthreads();

    int weO = 0;
    float4 weP = make_float4(0.f, 0.f, 0.f, 0.f);
#pragma unroll
    for (int w = 0; w < 8; w++) {
        if (w < wid) {
            weO += waggO[w];
            weP.x += waggP[w].x; weP.y += waggP[w].y;
            weP.z += waggP[w].z; weP.w += waggP[w].w;
        }
    }

    int carO = s_carO;
    float4 carP = s_carP;
    if (tid == 0 && tile == 0) {
        g_S[rowoff] = 0;
        g_Bnd[rowoff] = make_float4(0.f, 0.f, 0.f, 0.f);
    }

    int id = carO + weO + exO;
    float4 pex = make_float4(carP.x + weP.x + exP.x, carP.y + weP.y + exP.y,
                             carP.z + weP.z + exP.z, carP.w + weP.w + exP.w);
#pragma unroll
    for (int i = 0; i < 8; i++) {
        id += ol[i];
        g_segids[ebase + i] = (unsigned short)id;
        if (ol[i]) {
            g_S[rowoff + id] = (int)(ebase + i - rowbase);
            g_Bnd[rowoff + id] = pex;
        }
        pex.x += pl[i].x; pex.y += pl[i].y; pex.z += pl[i].z; pex.w += pl[i].w;
    }

    if (tid == 255 && tile == NT - 1) {
        g_nOn[row] = id;
        g_S[rowoff + id + 1]   = Tn;
        g_Bnd[rowoff + id + 1] = pex;
    }
}

// =====================================================================
// K3: per-segment coefficient tables (32 blocks; all MUFU here)
// =====================================================================
__global__ void __launch_bounds__(256) k_segc() {
    int srow = blockIdx.x;
    int ro0 = srow * SEGCAP;
    int nOn = g_nOn[srow];
    for (int s = threadIdx.x; s <= nOn; s += 256) {
        int r2 = ro0 + s;
        float4 B0 = g_Bnd[r2], B1 = g_Bnd[r2 + 1];
        float d2 = (float)(g_S[r2 + 1] - g_S[r2]);
        float invc = __fdividef(1.f, fmaxf(d2, 1.f));
        float dist = 0.1f * exp2f(fast_sigmoid((B1.x - B0.x) * invc) * LOG2_20_F);
        float wmod = fast_sigmoid((B1.y - B0.y) * invc);
        float qmod = fast_sigmoid((B1.z - B0.z) * invc);
        float mu   = fast_sigmoid((B1.w - B0.w) * invc);

        float w = MIN_W_F * exp2f(wmod * LOG2_400_F);
        float q = 0.1f * exp2f(qmod * LOG2_20_F);
        float sh, ch;
        __sincosf(0.5f * w, &sh, &ch);
        float omc = 2.f * sh * sh;      // 1 - cos(w)
        float cw = 1.f - omc;
        float sw = 2.f * sh * ch;
        float alpha = __fdividef(sw, 2.f * q);
        float inva0 = __fdividef(1.f, 1.f + alpha);
        float b0 = 0.5f * omc * inva0;
        float b1c = omc * inva0;
        float a1 = -2.f * cw * inva0;
        float a2 = (1.f - alpha) * inva0;

        g_segA[r2] = make_float4(-a1, -a2, b1c - a1 * b0, b0 - a2 * b0);
        g_segB[r2] = make_float2(b0, mu);
        g_segD[r2] = dist;
    }
}

// =====================================================================
// helpers
// =====================================================================
__device__ __forceinline__ void unpack_ids(uint4 sv, int ids[SPT]) {
    ids[0] = sv.x & 0xffff; ids[1] = sv.x >> 16;
    ids[2] = sv.y & 0xffff; ids[3] = sv.y >> 16;
    ids[4] = sv.z & 0xffff; ids[5] = sv.z >> 16;
    ids[6] = sv.w & 0xffff; ids[7] = sv.w >> 16;
}

__device__ __forceinline__ void compose_thread(const int ids[SPT], bool uni,
        int rowoff, float4 T0, const float xc[SPT],
        float& A00, float& A01, float& A10, float& A11, float& c1, float& c2) {
    float4 T = T0;
    A00 = 1.f; A01 = 0.f; A10 = 0.f; A11 = 1.f; c1 = 0.f; c2 = 0.f;
#pragma unroll
    for (int i = 0; i < SPT; i++) {
        if (!uni && i) T = g_segA[rowoff + ids[i]];
        float n00 = fmaf(T.x, A00, A10);
        float n01 = fmaf(T.x, A01, A11);
        float n10 = T.y * A00;
        float n11 = T.y * A01;
        float t1  = fmaf(T.x, c1, c2) + T.z * xc[i];
        float t2  = fmaf(T.y, c1, T.w * xc[i]);
        A00 = n00; A01 = n01; A10 = n10; A11 = n11; c1 = t1; c2 = t2;
    }
}

// =====================================================================
// K4: stage x*dist into swizzled smem + comb + chunk aggregate
// =====================================================================
__global__ void __launch_bounds__(BTH) k_scanA(const float* __restrict__ x,
                                               const float* __restrict__ f0) {
    __shared__ float sxd[SWSZ];
    __shared__ float wagg[8][6];

    int tid = threadIdx.x, blk = blockIdx.x;
    int lane = tid & 31, wid = tid >> 5;
    int base = blk * CHUNKN;
    int t0 = base & (Tn - 1);
    int rowoff = (base >> 16) * SEGCAP;

    // stage xd = x*dist over [base-LAG, base+CHUNKN)
#pragma unroll
    for (int k = tid; k < WIN / 4; k += BTH) {
        int off = k << 2;
        float4 v = make_float4(0.f, 0.f, 0.f, 0.f);
        if (t0 + off >= LAG) {
            int g = base - LAG + off;
            float4 xv = *(const float4*)&x[g];
            uint2 sv = *(const uint2*)&g_segids[g];
            v.x = xv.x * g_segD[rowoff + (int)(sv.x & 0xffff)];
            v.y = xv.y * g_segD[rowoff + (int)(sv.x >> 16)];
            v.z = xv.z * g_segD[rowoff + (int)(sv.y & 0xffff)];
            v.w = xv.w * g_segD[rowoff + (int)(sv.y >> 16)];
        }
        sxd[SW(off)]     = v.x;
        sxd[SW(off + 1)] = v.y;
        sxd[SW(off + 2)] = v.z;
        sxd[SW(off + 3)] = v.w;
    }
    __syncthreads();

    int lbase = tid * SPT;
    int gbase = base + lbase;
    int ids[SPT];
    unpack_ids(*(const uint4*)&g_segids[gbase], ids);
    bool uni = (ids[0] == ids[SPT - 1]);
    float4 T = g_segA[rowoff + ids[0]];
    float2 Bc = g_segB[rowoff + ids[0]];

    float4 f0a = *(const float4*)&f0[gbase];
    float4 f0b = *(const float4*)&f0[gbase + 4];
    float f0v[SPT] = { f0a.x, f0a.y, f0a.z, f0a.w, f0b.x, f0b.y, f0b.z, f0b.w };

    float xc[SPT];
#pragma unroll
    for (int i = 0; i < SPT; i++) {
        if (!uni && i) Bc = g_segB[rowoff + ids[i]];
        float p = f0v[i] * Bc.y;
        float z = floorf(p);
        float alfa = p - z;
        int zi = (int)z;
        int li = lbase + i + LAG;
        float x1 = sxd[SW(li - zi - 1)];
        float x2 = sxd[SW(li - zi - 2)];
        xc[i] = sxd[SW(li)] - (1.f - alfa) * x1 - alfa * x2;
    }
    *(float4*)&g_xc[gbase]     = make_float4(xc[0], xc[1], xc[2], xc[3]);
    *(float4*)&g_xc[gbase + 4] = make_float4(xc[4], xc[5], xc[6], xc[7]);

    float A00, A01, A10, A11, c1, c2;
    compose_thread(ids, uni, rowoff, T, xc, A00, A01, A10, A11, c1, c2);

    // warp ordered tree reduce (lane 0 ends with compose of lanes 0..31)
#pragma unroll
    for (int off = 1; off < 32; off <<= 1) {
        float L00 = __shfl_down_sync(~0u, A00, off);
        float L01 = __shfl_down_sync(~0u, A01, off);
        float L10 = __shfl_down_sync(~0u, A10, off);
        float L11 = __shfl_down_sync(~0u, A11, off);
        float Lc1 = __shfl_down_sync(~0u, c1, off);
        float Lc2 = __shfl_down_sync(~0u, c2, off);
        float N00, N01, N10, N11, Nc1, Nc2;
        COMPOSE(A00,A01,A10,A11,c1,c2, L00,L01,L10,L11,Lc1,Lc2,
                N00,N01,N10,N11,Nc1,Nc2);
        A00 = N00; A01 = N01; A10 = N10; A11 = N11; c1 = Nc1; c2 = Nc2;
    }
    if (lane == 0) {
        wagg[wid][0] = A00; wagg[wid][1] = A01; wagg[wid][2] = A10;
        wagg[wid][3] = A11; wagg[wid][4] = c1;  wagg[wid][5] = c2;
    }
    __syncthreads();
    if (wid == 0 && lane < 8) {
        float W00 = wagg[lane][0], W01 = wagg[lane][1], W10 = wagg[lane][2];
        float W11 = wagg[lane][3], Wc1 = wagg[lane][4], Wc2 = wagg[lane][5];
#pragma unroll
        for (int off = 1; off < 8; off <<= 1) {
            float L00 = __shfl_down_sync(0xffu, W00, off);
            float L01 = __shfl_down_sync(0xffu, W01, off);
            float L10 = __shfl_down_sync(0xffu, W10, off);
            float L11 = __shfl_down_sync(0xffu, W11, off);
            float Lc1 = __shfl_down_sync(0xffu, Wc1, off);
            float Lc2 = __shfl_down_sync(0xffu, Wc2, off);
            float N00, N01, N10, N11, Nc1, Nc2;
            COMPOSE(W00,W01,W10,W11,Wc1,Wc2, L00,L01,L10,L11,Lc1,Lc2,
                    N00,N01,N10,N11,Nc1,Nc2);
            W00 = N00; W01 = N01; W10 = N10; W11 = N11; Wc1 = Nc1; Wc2 = Nc2;
        }
        if (lane == 0) {
            g_chunkM[blk] = make_float4(W00, W01, W10, W11);
            g_chunkC[blk] = make_float2(Wc1, Wc2);
        }
    }
}

// =====================================================================
// K5: replay from xc — shfl scans only, one syncthreads
// =====================================================================
__global__ void __launch_bounds__(BTH) k_replay(float* __restrict__ out) {
    __shared__ float wagg[8][6];
    __shared__ float2 s_cin;

    int tid = threadIdx.x, lane = tid & 31, wid = tid >> 5;
    int blk = blockIdx.x;
    int base = blk * CHUNKN;
    int rowoff = (base >> 16) * SEGCAP;
    int gbase = base + tid * SPT;

    int ids[SPT];
    unpack_ids(*(const uint4*)&g_segids[gbase], ids);
    bool uni = (ids[0] == ids[SPT - 1]);
    float4 T0 = g_segA[rowoff + ids[0]];

    float4 xa = *(const float4*)&g_xc[gbase];
    float4 xb = *(const float4*)&g_xc[gbase + 4];
    float xc[SPT] = { xa.x, xa.y, xa.z, xa.w, xb.x, xb.y, xb.z, xb.w };

    float I00, I01, I10, I11, Ic1, Ic2;
    compose_thread(ids, uni, rowoff, T0, xc, I00, I01, I10, I11, Ic1, Ic2);

    // warp inclusive KS
#pragma unroll
    for (int off = 1; off < 32; off <<= 1) {
        float E00 = __shfl_up_sync(~0u, I00, off);
        float E01 = __shfl_up_sync(~0u, I01, off);
        float E10 = __shfl_up_sync(~0u, I10, off);
        float E11 = __shfl_up_sync(~0u, I11, off);
        float Ec1 = __shfl_up_sync(~0u, Ic1, off);
        float Ec2 = __shfl_up_sync(~0u, Ic2, off);
        if (lane >= off) {
            float N00, N01, N10, N11, Nc1, Nc2;
            COMPOSE(E00,E01,E10,E11,Ec1,Ec2, I00,I01,I10,I11,Ic1,Ic2,
                    N00,N01,N10,N11,Nc1,Nc2);
            I00 = N00; I01 = N01; I10 = N10; I11 = N11; Ic1 = Nc1; Ic2 = Nc2;
        }
    }
    // lane-exclusive
    float X00 = __shfl_up_sync(~0u, I00, 1);
    float X01 = __shfl_up_sync(~0u, I01, 1);
    float X10 = __shfl_up_sync(~0u, I10, 1);
    float X11 = __shfl_up_sync(~0u, I11, 1);
    float Xc1 = __shfl_up_sync(~0u, Ic1, 1);
    float Xc2 = __shfl_up_sync(~0u, Ic2, 1);
    if (lane == 0) { X00 = 1.f; X01 = 0.f; X10 = 0.f; X11 = 1.f; Xc1 = 0.f; Xc2 = 0.f; }
    if (lane == 31) {
        wagg[wid][0] = I00; wagg[wid][1] = I01; wagg[wid][2] = I10;
        wagg[wid][3] = I11; wagg[wid][4] = Ic1; wagg[wid][5] = Ic2;
    }

    // warp 0: incoming chunk state from predecessor aggregates
    if (wid == 0) {
        int chunk = blk & (NCHUNK - 1);
        int rowBlk = blk - chunk;
        float T00 = 1.f, T01 = 0.f, T10 = 0.f, T11 = 1.f, Tc1 = 0.f, Tc2 = 0.f;
        if (lane < chunk) {
            float4 M = g_chunkM[rowBlk + lane];
            float2 C = g_chunkC[rowBlk + lane];
            T00 = M.x; T01 = M.y; T10 = M.z; T11 = M.w; Tc1 = C.x; Tc2 = C.y;
        }
#pragma unroll
        for (int off = 1; off < 32; off <<= 1) {
            float E00 = __shfl_up_sync(~0u, T00, off);
            float E01 = __shfl_up_sync(~0u, T01, off);
            float E10 = __shfl_up_sync(~0u, T10, off);
            float E11 = __shfl_up_sync(~0u, T11, off);
            float Ec1 = __shfl_up_sync(~0u, Tc1, off);
            float Ec2 = __shfl_up_sync(~0u, Tc2, off);
            if (lane >= off) {
                float N00, N01, N10, N11, Nc1, Nc2;
                COMPOSE(E00,E01,E10,E11,Ec1,Ec2, T00,T01,T10,T11,Tc1,Tc2,
                        N00,N01,N10,N11,Nc1,Nc2);
                T00 = N00; T01 = N01; T10 = N10; T11 = N11; Tc1 = Nc1; Tc2 = Nc2;
            }
        }
        float i1 = 0.f, i2 = 0.f;
        if (chunk > 0) {
            i1 = __shfl_sync(~0u, Tc1, chunk - 1);
            i2 = __shfl_sync(~0u, Tc2, chunk - 1);
        }
        if (lane == 0) s_cin = make_float2(i1, i2);
    }
    __syncthreads();

    // incoming state: cin -> warp-exclusive -> lane-exclusive (apply to vec)
    float2 cin = s_cin;
    float s1 = cin.x, s2 = cin.y;
#pragma unroll
    for (int w = 0; w < 8; w++) {
        if (w < wid) {
            float n1 = fmaf(wagg[w][0], s1, fmaf(wagg[w][1], s2, wagg[w][4]));
            float n2 = fmaf(wagg[w][2], s1, fmaf(wagg[w][3], s2, wagg[w][5]));
            s1 = n1; s2 = n2;
        }
    }
    float st1 = fmaf(X00, s1, fmaf(X01, s2, Xc1));
    float st2 = fmaf(X10, s1, fmaf(X11, s2, Xc2));

    // replay
    float4 T = T0;
    float2 Bc = g_segB[rowoff + ids[0]];
    float ov[SPT];
#pragma unroll
    for (int i = 0; i < SPT; i++) {
        if (!uni && i) { T = g_segA[rowoff + ids[i]]; Bc = g_segB[rowoff + ids[i]]; }
        ov[i] = fmaf(Bc.x, xc[i], st1);
        float n1 = fmaf(T.x, st1, st2) + T.z * xc[i];
        float n2 = fmaf(T.y, st1, T.w * xc[i]);
        st1 = n1; st2 = n2;
    }
    *(float4*)&out[gbase]     = make_float4(ov[0], ov[1], ov[2], ov[3]);
    *(float4*)&out[gbase + 4] = make_float4(ov[4], ov[5], ov[6], ov[7]);
}

// =====================================================================
extern "C" void kernel_launch(void* const* d_in, const int* in_sizes, int n_in,
                              void* d_out, int out_size) {
    const float* f0     = (const float*)d_in[0];
    const float* x      = (const float*)d_in[1];
    const float* params = (const float*)d_in[2];
    const int*   onsets = (const int*)d_in[3];
    float* out = (float*)d_out;

    k_tile<<<Bn * NT, 256>>>((const int4*)onsets, (const float4*)params);
    k_ids<<<Bn * NT, 256>>>((const int4*)onsets, (const float4*)params);
    k_segc<<<Bn, 256>>>();
    k_scanA<<<Bn * NCHUNK, BTH>>>(x, f0);
    k_replay<<<Bn * NCHUNK, BTH>>>(out);
}

// round 11
// speedup vs baseline: 1.3226x; 1.1269x over previous
#include <cuda_runtime.h>

#define Bn 32
#define Tn 65536
#define TILE 2048
#define NT 32              /* tiles per row */
#define SEGCAP (Tn + 2)
#define NCHUNK 32
#define BTH 256
#define SPT 8              /* samples per thread in scan kernels */
#define LAG 256            /* staged history for comb (max lag ~202) */
#define CHUNKN (BTH * SPT) /* 2048 samples per scan block */
#define WIN (LAG + CHUNKN)
#define SWSZ (WIN + (WIN >> 5) + 4)

// ---------------- scratch (device globals) ----------------
static __device__ int    g_tO[Bn * NT];
static __device__ float4 g_tP[Bn * NT];
static __device__ int    g_nOn[Bn];
static __device__ unsigned short g_segids[Bn * Tn];  // 4 MB
static __device__ int    g_S[Bn * SEGCAP];
static __device__ float4 g_Bnd[Bn * SEGCAP];
static __device__ float4 g_segA[Bn * SEGCAP];        // m00, m10, v1, v2
static __device__ float2 g_segB[Bn * SEGCAP];        // b0, mu
static __device__ float  g_segD[Bn * SEGCAP];        // dist
static __device__ float  g_xc[Bn * Tn];              // 8 MB (comb output)
static __device__ float4 g_chunkM[Bn * NCHUNK];
static __device__ float2 g_chunkC[Bn * NCHUNK];

#define MIN_W_F     0.007853981633974483f
#define LOG2_400_F  8.643856189774724f
#define LOG2_20_F   4.321928094887363f

__device__ __forceinline__ float fast_sigmoid(float v) {
    return __fdividef(1.0f, 1.0f + __expf(-v));
}
__device__ __forceinline__ int SW(int j) { return j + (j >> 5); }
__device__ __forceinline__ void pdl_wait() {
    asm volatile("griddepcontrol.wait;" ::: "memory");
}

// N = L after E  (2x2 affine compose)
#define COMPOSE(E00,E01,E10,E11,Ec1,Ec2, L00,L01,L10,L11,Lc1,Lc2, \
                N00,N01,N10,N11,Nc1,Nc2)                          \
    do {                                                          \
        N00 = fmaf(L00, E00, L01 * E10);                          \
        N01 = fmaf(L00, E01, L01 * E11);                          \
        N10 = fmaf(L10, E00, L11 * E10);                          \
        N11 = fmaf(L10, E01, L11 * E11);                          \
        Nc1 = fmaf(L00, Ec1, fmaf(L01, Ec2, Lc1));                \
        Nc2 = fmaf(L10, Ec1, fmaf(L11, Ec2, Lc2));                \
    } while (0)

// =====================================================================
// K1: per-tile totals (coalesced, vectorized)
// =====================================================================
__global__ void __launch_bounds__(256) k_tile(const int4* __restrict__ onsets4,
                                              const float4* __restrict__ params) {
    int blk = blockIdx.x;
    int row = blk >> 5, tile = blk & (NT - 1);
    long base = (long)row * Tn + (long)tile * TILE;
    int tid = threadIdx.x;

    int o = 0;
    float4 ps = make_float4(0.f, 0.f, 0.f, 0.f);
#pragma unroll
    for (int k = 0; k < 2; k++) {
        int4 v = onsets4[(base >> 2) + k * 256 + tid];
        o += v.x + v.y + v.z + v.w;
    }
#pragma unroll
    for (int r = 0; r < 8; r++) {
        float4 p = params[base + r * 256 + tid];
        ps.x += p.x; ps.y += p.y; ps.z += p.z; ps.w += p.w;
    }
#pragma unroll
    for (int off = 16; off; off >>= 1) {
        o    += __shfl_down_sync(~0u, o, off);
        ps.x += __shfl_down_sync(~0u, ps.x, off);
        ps.y += __shfl_down_sync(~0u, ps.y, off);
        ps.z += __shfl_down_sync(~0u, ps.z, off);
        ps.w += __shfl_down_sync(~0u, ps.w, off);
    }
    __shared__ int    so[8];
    __shared__ float4 sp[8];
    int lane = tid & 31, wid = tid >> 5;
    if (lane == 0) { so[wid] = o; sp[wid] = ps; }
    __syncthreads();
    if (tid == 0) {
        int ot = 0; float4 pt = make_float4(0.f, 0.f, 0.f, 0.f);
#pragma unroll
        for (int w = 0; w < 8; w++) {
            ot += so[w];
            pt.x += sp[w].x; pt.y += sp[w].y; pt.z += sp[w].z; pt.w += sp[w].w;
        }
        g_tO[blk] = ot;
        g_tP[blk] = pt;
    }
}

// =====================================================================
// K2: segids + boundary scatter (PDL: loads own data before waiting)
// =====================================================================
__global__ void __launch_bounds__(256) k_ids(const int4* __restrict__ onsets4,
                                             const float4* __restrict__ params) {
    int blk = blockIdx.x;
    int row = blk >> 5, tile = blk & (NT - 1);
    long rowbase = (long)row * Tn;
    long base = rowbase + (long)tile * TILE;
    int tid = threadIdx.x, lane = tid & 31, wid = tid >> 5;
    int rowoff = row * SEGCAP;

    __shared__ int    waggO[8];
    __shared__ float4 waggP[8];
    __shared__ int    s_carO;
    __shared__ float4 s_carP;

    // independent prologue: own 8 samples (overlaps k_tile tail via PDL)
    long ebase = base + (long)tid * 8;
    int4 oa = onsets4[ebase >> 2];
    int4 ob = onsets4[(ebase >> 2) + 1];
    int ol[8] = { oa.x, oa.y, oa.z, oa.w, ob.x, ob.y, ob.z, ob.w };
    float4 pl[8];
#pragma unroll
    for (int i = 0; i < 8; i++) pl[i] = params[ebase + i];

    pdl_wait();   // g_tO/g_tP must be complete beyond this point

    if (wid == 0) {
        int co = 0;
        float4 cp = make_float4(0.f, 0.f, 0.f, 0.f);
        if (lane < tile) {
            int pb = (row << 5) + lane;
            co = g_tO[pb];
            cp = g_tP[pb];
        }
#pragma unroll
        for (int off = 16; off; off >>= 1) {
            co   += __shfl_down_sync(~0u, co, off);
            cp.x += __shfl_down_sync(~0u, cp.x, off);
            cp.y += __shfl_down_sync(~0u, cp.y, off);
            cp.z += __shfl_down_sync(~0u, cp.z, off);
            cp.w += __shfl_down_sync(~0u, cp.w, off);
        }
        if (lane == 0) { s_carO = co; s_carP = cp; }
    }

    int totO = 0;
    float4 totP = make_float4(0.f, 0.f, 0.f, 0.f);
#pragma unroll
    for (int i = 0; i < 8; i++) {
        totO += ol[i];
        totP.x += pl[i].x; totP.y += pl[i].y; totP.z += pl[i].z; totP.w += pl[i].w;
    }

    int inO = totO;
    float4 inP = totP;
#pragma unroll
    for (int off = 1; off < 32; off <<= 1) {
        int   eo = __shfl_up_sync(~0u, inO, off);
        float a = __shfl_up_sync(~0u, inP.x, off);
        float b = __shfl_up_sync(~0u, inP.y, off);
        float c = __shfl_up_sync(~0u, inP.z, off);
        float d = __shfl_up_sync(~0u, inP.w, off);
        if (lane >= off) { inO += eo; inP.x += a; inP.y += b; inP.z += c; inP.w += d; }
    }
    int exO = __shfl_up_sync(~0u, inO, 1);
    float4 exP;
    exP.x = __shfl_up_sync(~0u, inP.x, 1);
    exP.y = __shfl_up_sync(~0u, inP.y, 1);
    exP.z = __shfl_up_sync(~0u, inP.z, 1);
    exP.w = __shfl_up_sync(~0u, inP.w, 1);
    if (lane == 0) { exO = 0; exP = make_float4(0.f, 0.f, 0.f, 0.f); }
    if (lane == 31) { waggO[wid] = inO; waggP[wid] = inP; }
    __syncthreads();

    int weO = 0;
    float4 weP = make_float4(0.f, 0.f, 0.f, 0.f);
#pragma unroll
    for (int w = 0; w < 8; w++) {
        if (w < wid) {
            weO += waggO[w];
            weP.x += waggP[w].x; weP.y += waggP[w].y;
            weP.z += waggP[w].z; weP.w += waggP[w].w;
        }
    }

    int carO = s_carO;
    float4 carP = s_carP;
    if (tid == 0 && tile == 0) {
        g_S[rowoff] = 0;
        g_Bnd[rowoff] = make_float4(0.f, 0.f, 0.f, 0.f);
    }

    int id = carO + weO + exO;
    float4 pex = make_float4(carP.x + weP.x + exP.x, carP.y + weP.y + exP.y,
                             carP.z + weP.z + exP.z, carP.w + weP.w + exP.w);
#pragma unroll
    for (int i = 0; i < 8; i++) {
        id += ol[i];
        g_segids[ebase + i] = (unsigned short)id;
        if (ol[i]) {
            g_S[rowoff + id] = (int)(ebase + i - rowbase);
            g_Bnd[rowoff + id] = pex;
        }
        pex.x += pl[i].x; pex.y += pl[i].y; pex.z += pl[i].z; pex.w += pl[i].w;
    }

    if (tid == 255 && tile == NT - 1) {
        g_nOn[row] = id;
        g_S[rowoff + id + 1]   = Tn;
        g_Bnd[rowoff + id + 1] = pex;
    }
}

// =====================================================================
// K3: per-segment coefficient tables (32 blocks; all MUFU here)
// =====================================================================
__global__ void __launch_bounds__(256) k_segc() {
    pdl_wait();
    int srow = blockIdx.x;
    int ro0 = srow * SEGCAP;
    int nOn = g_nOn[srow];
    for (int s = threadIdx.x; s <= nOn; s += 256) {
        int r2 = ro0 + s;
        float4 B0 = g_Bnd[r2], B1 = g_Bnd[r2 + 1];
        float d2 = (float)(g_S[r2 + 1] - g_S[r2]);
        float invc = __fdividef(1.f, fmaxf(d2, 1.f));
        float dist = 0.1f * exp2f(fast_sigmoid((B1.x - B0.x) * invc) * LOG2_20_F);
        float wmod = fast_sigmoid((B1.y - B0.y) * invc);
        float qmod = fast_sigmoid((B1.z - B0.z) * invc);
        float mu   = fast_sigmoid((B1.w - B0.w) * invc);

        float w = MIN_W_F * exp2f(wmod * LOG2_400_F);
        float q = 0.1f * exp2f(qmod * LOG2_20_F);
        float sh, ch;
        __sincosf(0.5f * w, &sh, &ch);
        float omc = 2.f * sh * sh;      // 1 - cos(w)
        float cw = 1.f - omc;
        float sw = 2.f * sh * ch;
        float alpha = __fdividef(sw, 2.f * q);
        float inva0 = __fdividef(1.f, 1.f + alpha);
        float b0 = 0.5f * omc * inva0;
        float b1c = omc * inva0;
        float a1 = -2.f * cw * inva0;
        float a2 = (1.f - alpha) * inva0;

        g_segA[r2] = make_float4(-a1, -a2, b1c - a1 * b0, b0 - a2 * b0);
        g_segB[r2] = make_float2(b0, mu);
        g_segD[r2] = dist;
    }
}

// =====================================================================
// helpers
// =====================================================================
__device__ __forceinline__ void unpack_ids(uint4 sv, int ids[SPT]) {
    ids[0] = sv.x & 0xffff; ids[1] = sv.x >> 16;
    ids[2] = sv.y & 0xffff; ids[3] = sv.y >> 16;
    ids[4] = sv.z & 0xffff; ids[5] = sv.z >> 16;
    ids[6] = sv.w & 0xffff; ids[7] = sv.w >> 16;
}

__device__ __forceinline__ void compose_thread(const int ids[SPT], bool uni,
        int rowoff, float4 T0, const float xc[SPT],
        float& A00, float& A01, float& A10, float& A11, float& c1, float& c2) {
    float4 T = T0;
    A00 = 1.f; A01 = 0.f; A10 = 0.f; A11 = 1.f; c1 = 0.f; c2 = 0.f;
#pragma unroll
    for (int i = 0; i < SPT; i++) {
        if (!uni && i) T = g_segA[rowoff + ids[i]];
        float n00 = fmaf(T.x, A00, A10);
        float n01 = fmaf(T.x, A01, A11);
        float n10 = T.y * A00;
        float n11 = T.y * A01;
        float t1  = fmaf(T.z, xc[i], fmaf(T.x, c1, c2));
        float t2  = fmaf(T.w, xc[i], T.y * c1);
        A00 = n00; A01 = n01; A10 = n10; A11 = n11; c1 = t1; c2 = t2;
    }
}

// =====================================================================
// K4: stage x*dist into swizzled smem + comb + chunk aggregate
// =====================================================================
__global__ void __launch_bounds__(BTH) k_scanA(const float* __restrict__ x,
                                               const float* __restrict__ f0) {
    __shared__ float sxd[SWSZ];
    __shared__ float wagg[8][6];

    int tid = threadIdx.x, blk = blockIdx.x;
    int lane = tid & 31, wid = tid >> 5;
    int base = blk * CHUNKN;
    int t0 = base & (Tn - 1);
    int rowoff = (base >> 16) * SEGCAP;
    int lbase = tid * SPT;
    int gbase = base + lbase;

    // independent prologue: f0 loads (overlap k_segc tail via PDL)
    float4 f0a = *(const float4*)&f0[gbase];
    float4 f0b = *(const float4*)&f0[gbase + 4];
    float f0v[SPT] = { f0a.x, f0a.y, f0a.z, f0a.w, f0b.x, f0b.y, f0b.z, f0b.w };

    pdl_wait();   // tables + segids complete beyond this point

    // stage xd = x*dist over [base-LAG, base+CHUNKN)
#pragma unroll
    for (int k = tid; k < WIN / 4; k += BTH) {
        int off = k << 2;
        float4 v = make_float4(0.f, 0.f, 0.f, 0.f);
        if (t0 + off >= LAG) {
            int g = base - LAG + off;
            float4 xv = *(const float4*)&x[g];
            uint2 sv = *(const uint2*)&g_segids[g];
            v.x = xv.x * g_segD[rowoff + (int)(sv.x & 0xffff)];
            v.y = xv.y * g_segD[rowoff + (int)(sv.x >> 16)];
            v.z = xv.z * g_segD[rowoff + (int)(sv.y & 0xffff)];
            v.w = xv.w * g_segD[rowoff + (int)(sv.y >> 16)];
        }
        sxd[SW(off)]     = v.x;
        sxd[SW(off + 1)] = v.y;
        sxd[SW(off + 2)] = v.z;
        sxd[SW(off + 3)] = v.w;
    }
    __syncthreads();

    int ids[SPT];
    unpack_ids(*(const uint4*)&g_segids[gbase], ids);
    bool uni = (ids[0] == ids[SPT - 1]);
    float4 T = g_segA[rowoff + ids[0]];
    float2 Bc = g_segB[rowoff + ids[0]];

    float xc[SPT];
#pragma unroll
    for (int i = 0; i < SPT; i++) {
        if (!uni && i) Bc = g_segB[rowoff + ids[i]];
        float p = f0v[i] * Bc.y;
        int zi = (int)p;                   // p > 0: trunc == floor
        float alfa = p - (float)zi;
        int li = lbase + i + LAG;
        float x1 = sxd[SW(li - zi - 1)];
        float x2 = sxd[SW(li - zi - 2)];
        xc[i] = fmaf(alfa, x1 - x2, sxd[SW(li)] - x1);
    }
    *(float4*)&g_xc[gbase]     = make_float4(xc[0], xc[1], xc[2], xc[3]);
    *(float4*)&g_xc[gbase + 4] = make_float4(xc[4], xc[5], xc[6], xc[7]);

    float A00, A01, A10, A11, c1, c2;
    compose_thread(ids, uni, rowoff, T, xc, A00, A01, A10, A11, c1, c2);

    // warp ordered tree reduce (lane 0 ends with compose of lanes 0..31)
#pragma unroll
    for (int off = 1; off < 32; off <<= 1) {
        float L00 = __shfl_down_sync(~0u, A00, off);
        float L01 = __shfl_down_sync(~0u, A01, off);
        float L10 = __shfl_down_sync(~0u, A10, off);
        float L11 = __shfl_down_sync(~0u, A11, off);
        float Lc1 = __shfl_down_sync(~0u, c1, off);
        float Lc2 = __shfl_down_sync(~0u, c2, off);
        float N00, N01, N10, N11, Nc1, Nc2;
        COMPOSE(A00,A01,A10,A11,c1,c2, L00,L01,L10,L11,Lc1,Lc2,
                N00,N01,N10,N11,Nc1,Nc2);
        A00 = N00; A01 = N01; A10 = N10; A11 = N11; c1 = Nc1; c2 = Nc2;
    }
    if (lane == 0) {
        wagg[wid][0] = A00; wagg[wid][1] = A01; wagg[wid][2] = A10;
        wagg[wid][3] = A11; wagg[wid][4] = c1;  wagg[wid][5] = c2;
    }
    __syncthreads();
    if (wid == 0 && lane < 8) {
        float W00 = wagg[lane][0], W01 = wagg[lane][1], W10 = wagg[lane][2];
        float W11 = wagg[lane][3], Wc1 = wagg[lane][4], Wc2 = wagg[lane][5];
#pragma unroll
        for (int off = 1; off < 8; off <<= 1) {
            float L00 = __shfl_down_sync(0xffu, W00, off);
            float L01 = __shfl_down_sync(0xffu, W01, off);
            float L10 = __shfl_down_sync(0xffu, W10, off);
            float L11 = __shfl_down_sync(0xffu, W11, off);
            float Lc1 = __shfl_down_sync(0xffu, Wc1, off);
            float Lc2 = __shfl_down_sync(0xffu, Wc2, off);
            float N00, N01, N10, N11, Nc1, Nc2;
            COMPOSE(W00,W01,W10,W11,Wc1,Wc2, L00,L01,L10,L11,Lc1,Lc2,
                    N00,N01,N10,N11,Nc1,Nc2);
            W00 = N00; W01 = N01; W10 = N10; W11 = N11; Wc1 = Nc1; Wc2 = Nc2;
        }
        if (lane == 0) {
            g_chunkM[blk] = make_float4(W00, W01, W10, W11);
            g_chunkC[blk] = make_float2(Wc1, Wc2);
        }
    }
}

// =====================================================================
// K5: replay from xc — shfl scans only, one syncthreads
// =====================================================================
__global__ void __launch_bounds__(BTH) k_replay(float* __restrict__ out) {
    __shared__ float wagg[8][6];
    __shared__ float2 s_cin;

    int tid = threadIdx.x, lane = tid & 31, wid = tid >> 5;
    int blk = blockIdx.x;
    int base = blk * CHUNKN;
    int rowoff = (base >> 16) * SEGCAP;
    int gbase = base + tid * SPT;

    pdl_wait();   // xc + chunk aggregates complete beyond this point

    int ids[SPT];
    unpack_ids(*(const uint4*)&g_segids[gbase], ids);
    bool uni = (ids[0] == ids[SPT - 1]);
    float4 T0 = g_segA[rowoff + ids[0]];

    float4 xa = *(const float4*)&g_xc[gbase];
    float4 xb = *(const float4*)&g_xc[gbase + 4];
    float xc[SPT] = { xa.x, xa.y, xa.z, xa.w, xb.x, xb.y, xb.z, xb.w };

    float I00, I01, I10, I11, Ic1, Ic2;
    compose_thread(ids, uni, rowoff, T0, xc, I00, I01, I10, I11, Ic1, Ic2);

    // warp inclusive KS
#pragma unroll
    for (int off = 1; off < 32; off <<= 1) {
        float E00 = __shfl_up_sync(~0u, I00, off);
        float E01 = __shfl_up_sync(~0u, I01, off);
        float E10 = __shfl_up_sync(~0u, I10, off);
        float E11 = __shfl_up_sync(~0u, I11, off);
        float Ec1 = __shfl_up_sync(~0u, Ic1, off);
        float Ec2 = __shfl_up_sync(~0u, Ic2, off);
        if (lane >= off) {
            float N00, N01, N10, N11, Nc1, Nc2;
            COMPOSE(E00,E01,E10,E11,Ec1,Ec2, I00,I01,I10,I11,Ic1,Ic2,
                    N00,N01,N10,N11,Nc1,Nc2);
            I00 = N00; I01 = N01; I10 = N10; I11 = N11; Ic1 = Nc1; Ic2 = Nc2;
        }
    }
    // lane-exclusive
    float X00 = __shfl_up_sync(~0u, I00, 1);
    float X01 = __shfl_up_sync(~0u, I01, 1);
    float X10 = __shfl_up_sync(~0u, I10, 1);
    float X11 = __shfl_up_sync(~0u, I11, 1);
    float Xc1 = __shfl_up_sync(~0u, Ic1, 1);
    float Xc2 = __shfl_up_sync(~0u, Ic2, 1);
    if (lane == 0) { X00 = 1.f; X01 = 0.f; X10 = 0.f; X11 = 1.f; Xc1 = 0.f; Xc2 = 0.f; }
    if (lane == 31) {
        wagg[wid][0] = I00; wagg[wid][1] = I01; wagg[wid][2] = I10;
        wagg[wid][3] = I11; wagg[wid][4] = Ic1; wagg[wid][5] = Ic2;
    }

    // warp 0: incoming chunk state from predecessor aggregates
    if (wid == 0) {
        int chunk = blk & (NCHUNK - 1);
        int rowBlk = blk - chunk;
        float T00 = 1.f, T01 = 0.f, T10 = 0.f, T11 = 1.f, Tc1 = 0.f, Tc2 = 0.f;
        if (lane < chunk) {
            float4 M = g_chunkM[rowBlk + lane];
            float2 C = g_chunkC[rowBlk + lane];
            T00 = M.x; T01 = M.y; T10 = M.z; T11 = M.w; Tc1 = C.x; Tc2 = C.y;
        }
#pragma unroll
        for (int off = 1; off < 32; off <<= 1) {
            float E00 = __shfl_up_sync(~0u, T00, off);
            float E01 = __shfl_up_sync(~0u, T01, off);
            float E10 = __shfl_up_sync(~0u, T10, off);
            float E11 = __shfl_up_sync(~0u, T11, off);
            float Ec1 = __shfl_up_sync(~0u, Tc1, off);
            float Ec2 = __shfl_up_sync(~0u, Tc2, off);
            if (lane >= off) {
                float N00, N01, N10, N11, Nc1, Nc2;
                COMPOSE(E00,E01,E10,E11,Ec1,Ec2, T00,T01,T10,T11,Tc1,Tc2,
                        N00,N01,N10,N11,Nc1,Nc2);
                T00 = N00; T01 = N01; T10 = N10; T11 = N11; Tc1 = Nc1; Tc2 = Nc2;
            }
        }
        float i1 = 0.f, i2 = 0.f;
        if (chunk > 0) {
            i1 = __shfl_sync(~0u, Tc1, chunk - 1);
            i2 = __shfl_sync(~0u, Tc2, chunk - 1);
        }
        if (lane == 0) s_cin = make_float2(i1, i2);
    }
    __syncthreads();

    // incoming state: cin -> warp-exclusive -> lane-exclusive (apply to vec)
    float2 cin = s_cin;
    float s1 = cin.x, s2 = cin.y;
#pragma unroll
    for (int w = 0; w < 8; w++) {
        if (w < wid) {
            float n1 = fmaf(wagg[w][0], s1, fmaf(wagg[w][1], s2, wagg[w][4]));
            float n2 = fmaf(wagg[w][2], s1, fmaf(wagg[w][3], s2, wagg[w][5]));
            s1 = n1; s2 = n2;
        }
    }
    float st1 = fmaf(X00, s1, fmaf(X01, s2, Xc1));
    float st2 = fmaf(X10, s1, fmaf(X11, s2, Xc2));

    // replay
    float4 T = T0;
    float2 Bc = g_segB[rowoff + ids[0]];
    float ov[SPT];
#pragma unroll
    for (int i = 0; i < SPT; i++) {
        if (!uni && i) { T = g_segA[rowoff + ids[i]]; Bc = g_segB[rowoff + ids[i]]; }
        ov[i] = fmaf(Bc.x, xc[i], st1);
        float n1 = fmaf(T.z, xc[i], fmaf(T.x, st1, st2));
        float n2 = fmaf(T.w, xc[i], T.y * st1);
        st1 = n1; st2 = n2;
    }
    *(float4*)&out[gbase]     = make_float4(ov[0], ov[1], ov[2], ov[3]);
    *(float4*)&out[gbase + 4] = make_float4(ov[4], ov[5], ov[6], ov[7]);
}

// =====================================================================
template <typename F, typename... Args>
static void launch_pdl(F fn, int grid, int block, Args... args) {
    cudaLaunchConfig_t cfg = {};
    cfg.gridDim = dim3(grid, 1, 1);
    cfg.blockDim = dim3(block, 1, 1);
    cudaLaunchAttribute attr[1];
    attr[0].id = cudaLaunchAttributeProgrammaticStreamSerialization;
    attr[0].val.programmaticStreamSerializationAllowed = 1;
    cfg.attrs = attr;
    cfg.numAttrs = 1;
    cudaLaunchKernelEx(&cfg, fn, args...);
}

extern "C" void kernel_launch(void* const* d_in, const int* in_sizes, int n_in,
                              void* d_out, int out_size) {
    const float* f0     = (const float*)d_in[0];
    const float* x      = (const float*)d_in[1];
    const float* params = (const float*)d_in[2];
    const int*   onsets = (const int*)d_in[3];
    float* out = (float*)d_out;

    k_tile<<<Bn * NT, 256>>>((const int4*)onsets, (const float4*)params);
    launch_pdl(k_ids,    Bn * NT,     256, (const int4*)onsets, (const float4*)params);
    launch_pdl(k_segc,   Bn,          256);
    launch_pdl(k_scanA,  Bn * NCHUNK, BTH, x, f0);
    launch_pdl(k_replay, Bn * NCHUNK, BTH, out);
}

// round 12
// speedup vs baseline: 1.4369x; 1.0865x over previous
#include <cuda_runtime.h>

#define Bn 32
#define Tn 65536
#define TILE 2048
#define NT 32              /* tiles per row */
#define SEGCAP (Tn + 2)
#define NCHUNK 32
#define BTH 256
#define SPT 8              /* samples per thread in scan kernels */
#define LAG 256            /* staged history for comb (max lag ~202) */
#define CHUNKN (BTH * SPT) /* 2048 samples per scan block */
#define WIN (LAG + CHUNKN)
#define SWSZ (WIN + (WIN >> 5) + 4)

// ---------------- scratch (device globals) ----------------
static __device__ int    g_tO[Bn * NT];
static __device__ float4 g_tP[Bn * NT];     // per-tile param totals (from k_ids)
static __device__ int    g_nOn[Bn];
static __device__ unsigned short g_segids[Bn * Tn];  // 4 MB
static __device__ int    g_S[Bn * SEGCAP];
static __device__ float4 g_Bnd[Bn * SEGCAP];         // TILE-LOCAL prefix at boundary
static __device__ float4 g_segA[Bn * SEGCAP];        // m00, m10, v1, v2
static __device__ float2 g_segB[Bn * SEGCAP];        // b0, mu
static __device__ float  g_segD[Bn * SEGCAP];        // dist
static __device__ float  g_xc[Bn * Tn];              // 8 MB (comb output)
static __device__ float4 g_chunkM[Bn * NCHUNK];
static __device__ float2 g_chunkC[Bn * NCHUNK];

#define MIN_W_F     0.007853981633974483f
#define LOG2_400_F  8.643856189774724f
#define LOG2_20_F   4.321928094887363f

__device__ __forceinline__ float fast_sigmoid(float v) {
    return __fdividef(1.0f, 1.0f + __expf(-v));
}
__device__ __forceinline__ int SW(int j) { return j + (j >> 5); }
__device__ __forceinline__ void pdl_wait() {
    asm volatile("griddepcontrol.wait;" ::: "memory");
}

// N = L after E  (2x2 affine compose)
#define COMPOSE(E00,E01,E10,E11,Ec1,Ec2, L00,L01,L10,L11,Lc1,Lc2, \
                N00,N01,N10,N11,Nc1,Nc2)                          \
    do {                                                          \
        N00 = fmaf(L00, E00, L01 * E10);                          \
        N01 = fmaf(L00, E01, L01 * E11);                          \
        N10 = fmaf(L10, E00, L11 * E10);                          \
        N11 = fmaf(L10, E01, L11 * E11);                          \
        Nc1 = fmaf(L00, Ec1, fmaf(L01, Ec2, Lc1));                \
        Nc2 = fmaf(L10, Ec1, fmaf(L11, Ec2, Lc2));                \
    } while (0)

// =====================================================================
// K1: per-tile ONSET totals only (8 MB read)
// =====================================================================
__global__ void __launch_bounds__(256) k_tile(const int4* __restrict__ onsets4) {
    int blk = blockIdx.x;
    long base4 = (long)blk * (TILE / 4);
    int tid = threadIdx.x;

    int o = 0;
#pragma unroll
    for (int k = 0; k < 2; k++) {
        int4 v = onsets4[base4 + k * 256 + tid];
        o += v.x + v.y + v.z + v.w;
    }
#pragma unroll
    for (int off = 16; off; off >>= 1)
        o += __shfl_down_sync(~0u, o, off);
    __shared__ int so[8];
    int lane = tid & 31, wid = tid >> 5;
    if (lane == 0) so[wid] = o;
    __syncthreads();
    if (tid == 0) {
        int ot = 0;
#pragma unroll
        for (int w = 0; w < 8; w++) ot += so[w];
        g_tO[blk] = ot;
    }
}

// =====================================================================
// K2: segids (packed u16x8 store) + TILE-LOCAL boundary prefixes +
//     per-tile param totals. Onset carry from K1 via PDL.
// =====================================================================
__global__ void __launch_bounds__(256) k_ids(const int4* __restrict__ onsets4,
                                             const float4* __restrict__ params) {
    int blk = blockIdx.x;
    int row = blk >> 5, tile = blk & (NT - 1);
    long rowbase = (long)row * Tn;
    long base = rowbase + (long)tile * TILE;
    int tid = threadIdx.x, lane = tid & 31, wid = tid >> 5;
    int rowoff = row * SEGCAP;

    __shared__ int    waggO[8];
    __shared__ float4 waggP[8];
    __shared__ int    s_carO;

    // independent prologue: own 8 samples (overlaps k_tile tail via PDL)
    long ebase = base + (long)tid * 8;
    int4 oa = onsets4[ebase >> 2];
    int4 ob = onsets4[(ebase >> 2) + 1];
    int ol[8] = { oa.x, oa.y, oa.z, oa.w, ob.x, ob.y, ob.z, ob.w };
    float4 pl[8];
#pragma unroll
    for (int i = 0; i < 8; i++) pl[i] = params[ebase + i];

    pdl_wait();   // g_tO complete beyond this point

    // warp 0: onset carry = sum of predecessor tile counts
    if (wid == 0) {
        int co = 0;
        if (lane < tile) co = g_tO[(row << 5) + lane];
#pragma unroll
        for (int off = 16; off; off >>= 1)
            co += __shfl_down_sync(~0u, co, off);
        if (lane == 0) s_carO = co;
    }

    int totO = 0;
    float4 totP = make_float4(0.f, 0.f, 0.f, 0.f);
#pragma unroll
    for (int i = 0; i < 8; i++) {
        totO += ol[i];
        totP.x += pl[i].x; totP.y += pl[i].y; totP.z += pl[i].z; totP.w += pl[i].w;
    }

    int inO = totO;
    float4 inP = totP;
#pragma unroll
    for (int off = 1; off < 32; off <<= 1) {
        int   eo = __shfl_up_sync(~0u, inO, off);
        float a = __shfl_up_sync(~0u, inP.x, off);
        float b = __shfl_up_sync(~0u, inP.y, off);
        float c = __shfl_up_sync(~0u, inP.z, off);
        float d = __shfl_up_sync(~0u, inP.w, off);
        if (lane >= off) { inO += eo; inP.x += a; inP.y += b; inP.z += c; inP.w += d; }
    }
    int exO = __shfl_up_sync(~0u, inO, 1);
    float4 exP;
    exP.x = __shfl_up_sync(~0u, inP.x, 1);
    exP.y = __shfl_up_sync(~0u, inP.y, 1);
    exP.z = __shfl_up_sync(~0u, inP.z, 1);
    exP.w = __shfl_up_sync(~0u, inP.w, 1);
    if (lane == 0) { exO = 0; exP = make_float4(0.f, 0.f, 0.f, 0.f); }
    if (lane == 31) { waggO[wid] = inO; waggP[wid] = inP; }
    __syncthreads();

    int weO = 0;
    float4 weP = make_float4(0.f, 0.f, 0.f, 0.f);
#pragma unroll
    for (int w = 0; w < 8; w++) {
        if (w < wid) {
            weO += waggO[w];
            weP.x += waggP[w].x; weP.y += waggP[w].y;
            weP.z += waggP[w].z; weP.w += waggP[w].w;
        }
    }

    int carO = s_carO;
    if (tid == 0 && tile == 0) {
        g_S[rowoff] = 0;
        g_Bnd[rowoff] = make_float4(0.f, 0.f, 0.f, 0.f);
    }

    int id = carO + weO + exO;
    // pex = TILE-LOCAL exclusive param prefix
    float4 pex = make_float4(weP.x + exP.x, weP.y + exP.y,
                             weP.z + exP.z, weP.w + exP.w);
    unsigned w01 = 0, w23 = 0, w45 = 0, w67 = 0;
#pragma unroll
    for (int i = 0; i < 8; i++) {
        id += ol[i];
        unsigned u = (unsigned)id & 0xffffu;
        if (i == 0) w01 = u;        else if (i == 1) w01 |= u << 16;
        else if (i == 2) w23 = u;   else if (i == 3) w23 |= u << 16;
        else if (i == 4) w45 = u;   else if (i == 5) w45 |= u << 16;
        else if (i == 6) w67 = u;   else              w67 |= u << 16;
        if (ol[i]) {
            g_S[rowoff + id] = (int)(ebase + i - rowbase);
            g_Bnd[rowoff + id] = pex;
        }
        pex.x += pl[i].x; pex.y += pl[i].y; pex.z += pl[i].z; pex.w += pl[i].w;
    }
    *(uint4*)&g_segids[ebase] = make_uint4(w01, w23, w45, w67);

    // last thread of each tile holds the tile param total
    if (tid == 255) {
        g_tP[blk] = pex;
        if (tile == NT - 1) {
            g_nOn[row] = id;
            g_S[rowoff + id + 1]   = Tn;
            g_Bnd[rowoff + id + 1] = pex;   // local total of tile 31
        }
    }
}

// =====================================================================
// K3: per-segment coefficient tables. Converts tile-local boundary
//     prefixes to global via the row's tile-offset scan.
// =====================================================================
__global__ void __launch_bounds__(256) k_segc() {
    __shared__ float4 tOff[NT];   // exclusive tile offsets

    pdl_wait();
    int srow = blockIdx.x;
    int ro0 = srow * SEGCAP;
    int tid = threadIdx.x, lane = tid & 31;

    if (tid < 32) {
        float4 p = g_tP[(srow << 5) + lane];
        float4 ip = p;
#pragma unroll
        for (int off = 1; off < 32; off <<= 1) {
            float a = __shfl_up_sync(~0u, ip.x, off);
            float b = __shfl_up_sync(~0u, ip.y, off);
            float c = __shfl_up_sync(~0u, ip.z, off);
            float d = __shfl_up_sync(~0u, ip.w, off);
            if (lane >= off) { ip.x += a; ip.y += b; ip.z += c; ip.w += d; }
        }
        tOff[lane] = make_float4(ip.x - p.x, ip.y - p.y, ip.z - p.z, ip.w - p.w);
    }
    __syncthreads();

    int nOn = g_nOn[srow];
    for (int s = tid; s <= nOn; s += 256) {
        int r2 = ro0 + s;
        int S0 = g_S[r2], S1 = g_S[r2 + 1];
        int t0 = S0 >> 11;
        int t1 = min(S1 >> 11, NT - 1);   // sentinel S1==Tn -> tile 31
        float4 O0 = tOff[t0], O1 = tOff[t1];
        float4 B0 = g_Bnd[r2], B1 = g_Bnd[r2 + 1];
        float sx = (O1.x + B1.x) - (O0.x + B0.x);
        float sy = (O1.y + B1.y) - (O0.y + B0.y);
        float sz = (O1.z + B1.z) - (O0.z + B0.z);
        float sw4 = (O1.w + B1.w) - (O0.w + B0.w);

        float invc = __fdividef(1.f, fmaxf((float)(S1 - S0), 1.f));
        float dist = 0.1f * exp2f(fast_sigmoid(sx * invc) * LOG2_20_F);
        float wmod = fast_sigmoid(sy * invc);
        float qmod = fast_sigmoid(sz * invc);
        float mu   = fast_sigmoid(sw4 * invc);

        float w = MIN_W_F * exp2f(wmod * LOG2_400_F);
        float q = 0.1f * exp2f(qmod * LOG2_20_F);
        float sh, ch;
        __sincosf(0.5f * w, &sh, &ch);
        float omc = 2.f * sh * sh;      // 1 - cos(w)
        float cw = 1.f - omc;
        float sw = 2.f * sh * ch;
        float alpha = __fdividef(sw, 2.f * q);
        float inva0 = __fdividef(1.f, 1.f + alpha);
        float b0 = 0.5f * omc * inva0;
        float b1c = omc * inva0;
        float a1 = -2.f * cw * inva0;
        float a2 = (1.f - alpha) * inva0;

        g_segA[r2] = make_float4(-a1, -a2, b1c - a1 * b0, b0 - a2 * b0);
        g_segB[r2] = make_float2(b0, mu);
        g_segD[r2] = dist;
    }
}

// =====================================================================
// helpers
// =====================================================================
__device__ __forceinline__ void unpack_ids(uint4 sv, int ids[SPT]) {
    ids[0] = sv.x & 0xffff; ids[1] = sv.x >> 16;
    ids[2] = sv.y & 0xffff; ids[3] = sv.y >> 16;
    ids[4] = sv.z & 0xffff; ids[5] = sv.z >> 16;
    ids[6] = sv.w & 0xffff; ids[7] = sv.w >> 16;
}

__device__ __forceinline__ void compose_thread(const int ids[SPT], bool uni,
        int rowoff, float4 T0, const float xc[SPT],
        float& A00, float& A01, float& A10, float& A11, float& c1, float& c2) {
    float4 T = T0;
    A00 = 1.f; A01 = 0.f; A10 = 0.f; A11 = 1.f; c1 = 0.f; c2 = 0.f;
#pragma unroll
    for (int i = 0; i < SPT; i++) {
        if (!uni && i) T = g_segA[rowoff + ids[i]];
        float n00 = fmaf(T.x, A00, A10);
        float n01 = fmaf(T.x, A01, A11);
        float n10 = T.y * A00;
        float n11 = T.y * A01;
        float t1  = fmaf(T.z, xc[i], fmaf(T.x, c1, c2));
        float t2  = fmaf(T.w, xc[i], T.y * c1);
        A00 = n00; A01 = n01; A10 = n10; A11 = n11; c1 = t1; c2 = t2;
    }
}

// =====================================================================
// K4: stage x*dist into swizzled smem + comb + chunk aggregate
// =====================================================================
__global__ void __launch_bounds__(BTH) k_scanA(const float* __restrict__ x,
                                               const float* __restrict__ f0) {
    __shared__ float sxd[SWSZ];
    __shared__ float wagg[8][6];

    int tid = threadIdx.x, blk = blockIdx.x;
    int lane = tid & 31, wid = tid >> 5;
    int base = blk * CHUNKN;
    int t0 = base & (Tn - 1);
    int rowoff = (base >> 16) * SEGCAP;
    int lbase = tid * SPT;
    int gbase = base + lbase;

    // independent prologue: f0 loads (overlap k_segc tail via PDL)
    float4 f0a = *(const float4*)&f0[gbase];
    float4 f0b = *(const float4*)&f0[gbase + 4];
    float f0v[SPT] = { f0a.x, f0a.y, f0a.z, f0a.w, f0b.x, f0b.y, f0b.z, f0b.w };

    pdl_wait();   // tables + segids complete beyond this point

    // stage xd = x*dist over [base-LAG, base+CHUNKN)
#pragma unroll
    for (int k = tid; k < WIN / 4; k += BTH) {
        int off = k << 2;
        float4 v = make_float4(0.f, 0.f, 0.f, 0.f);
        if (t0 + off >= LAG) {
            int g = base - LAG + off;
            float4 xv = *(const float4*)&x[g];
            uint2 sv = *(const uint2*)&g_segids[g];
            v.x = xv.x * g_segD[rowoff + (int)(sv.x & 0xffff)];
            v.y = xv.y * g_segD[rowoff + (int)(sv.x >> 16)];
            v.z = xv.z * g_segD[rowoff + (int)(sv.y & 0xffff)];
            v.w = xv.w * g_segD[rowoff + (int)(sv.y >> 16)];
        }
        sxd[SW(off)]     = v.x;
        sxd[SW(off + 1)] = v.y;
        sxd[SW(off + 2)] = v.z;
        sxd[SW(off + 3)] = v.w;
    }
    __syncthreads();

    int ids[SPT];
    unpack_ids(*(const uint4*)&g_segids[gbase], ids);
    bool uni = (ids[0] == ids[SPT - 1]);
    float4 T = g_segA[rowoff + ids[0]];
    float2 Bc = g_segB[rowoff + ids[0]];

    float xc[SPT];
#pragma unroll
    for (int i = 0; i < SPT; i++) {
        if (!uni && i) Bc = g_segB[rowoff + ids[i]];
        float p = f0v[i] * Bc.y;
        int zi = (int)p;                   // p > 0: trunc == floor
        float alfa = p - (float)zi;
        int li = lbase + i + LAG;
        float x1 = sxd[SW(li - zi - 1)];
        float x2 = sxd[SW(li - zi - 2)];
        xc[i] = fmaf(alfa, x1 - x2, sxd[SW(li)] - x1);
    }
    *(float4*)&g_xc[gbase]     = make_float4(xc[0], xc[1], xc[2], xc[3]);
    *(float4*)&g_xc[gbase + 4] = make_float4(xc[4], xc[5], xc[6], xc[7]);

    float A00, A01, A10, A11, c1, c2;
    compose_thread(ids, uni, rowoff, T, xc, A00, A01, A10, A11, c1, c2);

    // warp ordered tree reduce (lane 0 ends with compose of lanes 0..31)
#pragma unroll
    for (int off = 1; off < 32; off <<= 1) {
        float L00 = __shfl_down_sync(~0u, A00, off);
        float L01 = __shfl_down_sync(~0u, A01, off);
        float L10 = __shfl_down_sync(~0u, A10, off);
        float L11 = __shfl_down_sync(~0u, A11, off);
        float Lc1 = __shfl_down_sync(~0u, c1, off);
        float Lc2 = __shfl_down_sync(~0u, c2, off);
        float N00, N01, N10, N11, Nc1, Nc2;
        COMPOSE(A00,A01,A10,A11,c1,c2, L00,L01,L10,L11,Lc1,Lc2,
                N00,N01,N10,N11,Nc1,Nc2);
        A00 = N00; A01 = N01; A10 = N10; A11 = N11; c1 = Nc1; c2 = Nc2;
    }
    if (lane == 0) {
        wagg[wid][0] = A00; wagg[wid][1] = A01; wagg[wid][2] = A10;
        wagg[wid][3] = A11; wagg[wid][4] = c1;  wagg[wid][5] = c2;
    }
    __syncthreads();
    if (wid == 0 && lane < 8) {
        float W00 = wagg[lane][0], W01 = wagg[lane][1], W10 = wagg[lane][2];
        float W11 = wagg[lane][3], Wc1 = wagg[lane][4], Wc2 = wagg[lane][5];
#pragma unroll
        for (int off = 1; off < 8; off <<= 1) {
            float L00 = __shfl_down_sync(0xffu, W00, off);
            float L01 = __shfl_down_sync(0xffu, W01, off);
            float L10 = __shfl_down_sync(0xffu, W10, off);
            float L11 = __shfl_down_sync(0xffu, W11, off);
            float Lc1 = __shfl_down_sync(0xffu, Wc1, off);
            float Lc2 = __shfl_down_sync(0xffu, Wc2, off);
            float N00, N01, N10, N11, Nc1, Nc2;
            COMPOSE(W00,W01,W10,W11,Wc1,Wc2, L00,L01,L10,L11,Lc1,Lc2,
                    N00,N01,N10,N11,Nc1,Nc2);
            W00 = N00; W01 = N01; W10 = N10; W11 = N11; Wc1 = Nc1; Wc2 = Nc2;
        }
        if (lane == 0) {
            g_chunkM[blk] = make_float4(W00, W01, W10, W11);
            g_chunkC[blk] = make_float2(Wc1, Wc2);
        }
    }
}

// =====================================================================
// K5: replay from xc — shfl scans only, one syncthreads
// =====================================================================
__global__ void __launch_bounds__(BTH) k_replay(float* __restrict__ out) {
    __shared__ float wagg[8][6];
    __shared__ float2 s_cin;

    int tid = threadIdx.x, lane = tid & 31, wid = tid >> 5;
    int blk = blockIdx.x;
    int base = blk * CHUNKN;
    int rowoff = (base >> 16) * SEGCAP;
    int gbase = base + tid * SPT;

    pdl_wait();   // xc + chunk aggregates complete beyond this point

    int ids[SPT];
    unpack_ids(*(const uint4*)&g_segids[gbase], ids);
    bool uni = (ids[0] == ids[SPT - 1]);
    float4 T0 = g_segA[rowoff + ids[0]];

    float4 xa = *(const float4*)&g_xc[gbase];
    float4 xb = *(const float4*)&g_xc[gbase + 4];
    float xc[SPT] = { xa.x, xa.y, xa.z, xa.w, xb.x, xb.y, xb.z, xb.w };

    float I00, I01, I10, I11, Ic1, Ic2;
    compose_thread(ids, uni, rowoff, T0, xc, I00, I01, I10, I11, Ic1, Ic2);

    // warp inclusive KS
#pragma unroll
    for (int off = 1; off < 32; off <<= 1) {
        float E00 = __shfl_up_sync(~0u, I00, off);
        float E01 = __shfl_up_sync(~0u, I01, off);
        float E10 = __shfl_up_sync(~0u, I10, off);
        float E11 = __shfl_up_sync(~0u, I11, off);
        float Ec1 = __shfl_up_sync(~0u, Ic1, off);
        float Ec2 = __shfl_up_sync(~0u, Ic2, off);
        if (lane >= off) {
            float N00, N01, N10, N11, Nc1, Nc2;
            COMPOSE(E00,E01,E10,E11,Ec1,Ec2, I00,I01,I10,I11,Ic1,Ic2,
                    N00,N01,N10,N11,Nc1,Nc2);
            I00 = N00; I01 = N01; I10 = N10; I11 = N11; Ic1 = Nc1; Ic2 = Nc2;
        }
    }
    // lane-exclusive
    float X00 = __shfl_up_sync(~0u, I00, 1);
    float X01 = __shfl_up_sync(~0u, I01, 1);
    float X10 = __shfl_up_sync(~0u, I10, 1);
    float X11 = __shfl_up_sync(~0u, I11, 1);
    float Xc1 = __shfl_up_sync(~0u, Ic1, 1);
    float Xc2 = __shfl_up_sync(~0u, Ic2, 1);
    if (lane == 0) { X00 = 1.f; X01 = 0.f; X10 = 0.f; X11 = 1.f; Xc1 = 0.f; Xc2 = 0.f; }
    if (lane == 31) {
        wagg[wid][0] = I00; wagg[wid][1] = I01; wagg[wid][2] = I10;
        wagg[wid][3] = I11; wagg[wid][4] = Ic1; wagg[wid][5] = Ic2;
    }

    // warp 0: incoming chunk state from predecessor aggregates
    if (wid == 0) {
        int chunk = blk & (NCHUNK - 1);
        int rowBlk = blk - chunk;
        float T00 = 1.f, T01 = 0.f, T10 = 0.f, T11 = 1.f, Tc1 = 0.f, Tc2 = 0.f;
        if (lane < chunk) {
            float4 M = g_chunkM[rowBlk + lane];
            float2 C = g_chunkC[rowBlk + lane];
            T00 = M.x; T01 = M.y; T10 = M.z; T11 = M.w; Tc1 = C.x; Tc2 = C.y;
        }
#pragma unroll
        for (int off = 1; off < 32; off <<= 1) {
            float E00 = __shfl_up_sync(~0u, T00, off);
            float E01 = __shfl_up_sync(~0u, T01, off);
            float E10 = __shfl_up_sync(~0u, T10, off);
            float E11 = __shfl_up_sync(~0u, T11, off);
            float Ec1 = __shfl_up_sync(~0u, Tc1, off);
            float Ec2 = __shfl_up_sync(~0u, Tc2, off);
            if (lane >= off) {
                float N00, N01, N10, N11, Nc1, Nc2;
                COMPOSE(E00,E01,E10,E11,Ec1,Ec2, T00,T01,T10,T11,Tc1,Tc2,
                        N00,N01,N10,N11,Nc1,Nc2);
                T00 = N00; T01 = N01; T10 = N10; T11 = N11; Tc1 = Nc1; Tc2 = Nc2;
            }
        }
        float i1 = 0.f, i2 = 0.f;
        if (chunk > 0) {
            i1 = __shfl_sync(~0u, Tc1, chunk - 1);
            i2 = __shfl_sync(~0u, Tc2, chunk - 1);
        }
        if (lane == 0) s_cin = make_float2(i1, i2);
    }
    __syncthreads();

    // incoming state: cin -> warp-exclusive -> lane-exclusive (apply to vec)
    float2 cin = s_cin;
    float s1 = cin.x, s2 = cin.y;
#pragma unroll
    for (int w = 0; w < 8; w++) {
        if (w < wid) {
            float n1 = fmaf(wagg[w][0], s1, fmaf(wagg[w][1], s2, wagg[w][4]));
            float n2 = fmaf(wagg[w][2], s1, fmaf(wagg[w][3], s2, wagg[w][5]));
            s1 = n1; s2 = n2;
        }
    }
    float st1 = fmaf(X00, s1, fmaf(X01, s2, Xc1));
    float st2 = fmaf(X10, s1, fmaf(X11, s2, Xc2));

    // replay
    float4 T = T0;
    float2 Bc = g_segB[rowoff + ids[0]];
    float ov[SPT];
#pragma unroll
    for (int i = 0; i < SPT; i++) {
        if (!uni && i) { T = g_segA[rowoff + ids[i]]; Bc = g_segB[rowoff + ids[i]]; }
        ov[i] = fmaf(Bc.x, xc[i], st1);
        float n1 = fmaf(T.z, xc[i], fmaf(T.x, st1, st2));
        float n2 = fmaf(T.w, xc[i], T.y * st1);
        st1 = n1; st2 = n2;
    }
    *(float4*)&out[gbase]     = make_float4(ov[0], ov[1], ov[2], ov[3]);
    *(float4*)&out[gbase + 4] = make_float4(ov[4], ov[5], ov[6], ov[7]);
}

// =====================================================================
template <typename F, typename... Args>
static void launch_pdl(F fn, int grid, int block, Args... args) {
    cudaLaunchConfig_t cfg = {};
    cfg.gridDim = dim3(grid, 1, 1);
    cfg.blockDim = dim3(block, 1, 1);
    cudaLaunchAttribute attr[1];
    attr[0].id = cudaLaunchAttributeProgrammaticStreamSerialization;
    attr[0].val.programmaticStreamSerializationAllowed = 1;
    cfg.attrs = attr;
    cfg.numAttrs = 1;
    cudaLaunchKernelEx(&cfg, fn, args...);
}

extern "C" void kernel_launch(void* const* d_in, const int* in_sizes, int n_in,
                              void* d_out, int out_size) {
    const float* f0     = (const float*)d_in[0];
    const float* x      = (const float*)d_in[1];
    const float* params = (const float*)d_in[2];
    const int*   onsets = (const int*)d_in[3];
    float* out = (float*)d_out;

    k_tile<<<Bn * NT, 256>>>((const int4*)onsets);
    launch_pdl(k_ids,    Bn * NT,     256, (const int4*)onsets, (const float4*)params);
    launch_pdl(k_segc,   Bn,          256);
    launch_pdl(k_scanA,  Bn * NCHUNK, BTH, x, f0);
    launch_pdl(k_replay, Bn * NCHUNK, BTH, out);
}

// round 13
// speedup vs baseline: 1.4447x; 1.0054x over previous
#include <cuda_runtime.h>

#define Bn 32
#define Tn 65536
#define TILE 2048
#define NT 32              /* tiles per row */
#define SEGCAP (Tn + 2)
#define NCHUNK 32
#define BTH 256
#define SPT 8              /* samples per thread in scan kernels */
#define LAG 256            /* staged history for comb (max lag ~202) */
#define CHUNKN (BTH * SPT) /* 2048 samples per scan block */
#define WIN (LAG + CHUNKN)
#define SWSZ (WIN + (WIN >> 5) + 4)
#define NTH_TOT (Bn * Tn / SPT)   /* total scan threads = 262144 */

// ---------------- scratch (device globals) ----------------
static __device__ int    g_tO[Bn * NT];
static __device__ float4 g_tP[Bn * NT];
static __device__ int    g_nOn[Bn];
static __device__ unsigned short g_segids[Bn * Tn];  // 4 MB
static __device__ int    g_S[Bn * SEGCAP];
static __device__ float4 g_Bnd[Bn * SEGCAP];         // tile-local prefix at boundary
static __device__ float4 g_segA[Bn * SEGCAP];        // m00, m10, v1, v2
static __device__ float2 g_segB[Bn * SEGCAP];        // b0, mu
static __device__ float  g_segD[Bn * SEGCAP];        // dist
static __device__ float  g_xc[Bn * Tn];              // 8 MB (comb output)
static __device__ float4 g_pfxM[NTH_TOT];            // 4 MB  per-thread excl prefix (matrix)
static __device__ float2 g_pfxC[NTH_TOT];            // 2 MB  per-thread excl prefix (c)
static __device__ float4 g_chunkM[Bn * NCHUNK];
static __device__ float2 g_chunkC[Bn * NCHUNK];

#define MIN_W_F     0.007853981633974483f
#define LOG2_400_F  8.643856189774724f
#define LOG2_20_F   4.321928094887363f

__device__ __forceinline__ float fast_sigmoid(float v) {
    return __fdividef(1.0f, 1.0f + __expf(-v));
}
__device__ __forceinline__ int SW(int j) { return j + (j >> 5); }
__device__ __forceinline__ void pdl_wait() {
    asm volatile("griddepcontrol.wait;" ::: "memory");
}

// N = L after E  (2x2 affine compose)
#define COMPOSE(E00,E01,E10,E11,Ec1,Ec2, L00,L01,L10,L11,Lc1,Lc2, \
                N00,N01,N10,N11,Nc1,Nc2)                          \
    do {                                                          \
        N00 = fmaf(L00, E00, L01 * E10);                          \
        N01 = fmaf(L00, E01, L01 * E11);                          \
        N10 = fmaf(L10, E00, L11 * E10);                          \
        N11 = fmaf(L10, E01, L11 * E11);                          \
        Nc1 = fmaf(L00, Ec1, fmaf(L01, Ec2, Lc1));                \
        Nc2 = fmaf(L10, Ec1, fmaf(L11, Ec2, Lc2));                \
    } while (0)

// =====================================================================
// K1: per-tile ONSET totals only (8 MB read)
// =====================================================================
__global__ void __launch_bounds__(256) k_tile(const int4* __restrict__ onsets4) {
    int blk = blockIdx.x;
    long base4 = (long)blk * (TILE / 4);
    int tid = threadIdx.x;

    int o = 0;
#pragma unroll
    for (int k = 0; k < 2; k++) {
        int4 v = onsets4[base4 + k * 256 + tid];
        o += v.x + v.y + v.z + v.w;
    }
#pragma unroll
    for (int off = 16; off; off >>= 1)
        o += __shfl_down_sync(~0u, o, off);
    __shared__ int so[8];
    int lane = tid & 31, wid = tid >> 5;
    if (lane == 0) so[wid] = o;
    __syncthreads();
    if (tid == 0) {
        int ot = 0;
#pragma unroll
        for (int w = 0; w < 8; w++) ot += so[w];
        g_tO[blk] = ot;
    }
}

// =====================================================================
// K2: segids (packed u16x8) + tile-local boundary prefixes + tile totals
// =====================================================================
__global__ void __launch_bounds__(256) k_ids(const int4* __restrict__ onsets4,
                                             const float4* __restrict__ params) {
    int blk = blockIdx.x;
    int row = blk >> 5, tile = blk & (NT - 1);
    long rowbase = (long)row * Tn;
    long base = rowbase + (long)tile * TILE;
    int tid = threadIdx.x, lane = tid & 31, wid = tid >> 5;
    int rowoff = row * SEGCAP;

    __shared__ int    waggO[8];
    __shared__ float4 waggP[8];
    __shared__ int    s_carO;

    long ebase = base + (long)tid * 8;
    int4 oa = onsets4[ebase >> 2];
    int4 ob = onsets4[(ebase >> 2) + 1];
    int ol[8] = { oa.x, oa.y, oa.z, oa.w, ob.x, ob.y, ob.z, ob.w };
    float4 pl[8];
#pragma unroll
    for (int i = 0; i < 8; i++) pl[i] = params[ebase + i];

    pdl_wait();

    if (wid == 0) {
        int co = 0;
        if (lane < tile) co = g_tO[(row << 5) + lane];
#pragma unroll
        for (int off = 16; off; off >>= 1)
            co += __shfl_down_sync(~0u, co, off);
        if (lane == 0) s_carO = co;
    }

    int totO = 0;
    float4 totP = make_float4(0.f, 0.f, 0.f, 0.f);
#pragma unroll
    for (int i = 0; i < 8; i++) {
        totO += ol[i];
        totP.x += pl[i].x; totP.y += pl[i].y; totP.z += pl[i].z; totP.w += pl[i].w;
    }

    int inO = totO;
    float4 inP = totP;
#pragma unroll
    for (int off = 1; off < 32; off <<= 1) {
        int   eo = __shfl_up_sync(~0u, inO, off);
        float a = __shfl_up_sync(~0u, inP.x, off);
        float b = __shfl_up_sync(~0u, inP.y, off);
        float c = __shfl_up_sync(~0u, inP.z, off);
        float d = __shfl_up_sync(~0u, inP.w, off);
        if (lane >= off) { inO += eo; inP.x += a; inP.y += b; inP.z += c; inP.w += d; }
    }
    int exO = __shfl_up_sync(~0u, inO, 1);
    float4 exP;
    exP.x = __shfl_up_sync(~0u, inP.x, 1);
    exP.y = __shfl_up_sync(~0u, inP.y, 1);
    exP.z = __shfl_up_sync(~0u, inP.z, 1);
    exP.w = __shfl_up_sync(~0u, inP.w, 1);
    if (lane == 0) { exO = 0; exP = make_float4(0.f, 0.f, 0.f, 0.f); }
    if (lane == 31) { waggO[wid] = inO; waggP[wid] = inP; }
    __syncthreads();

    int weO = 0;
    float4 weP = make_float4(0.f, 0.f, 0.f, 0.f);
#pragma unroll
    for (int w = 0; w < 8; w++) {
        if (w < wid) {
            weO += waggO[w];
            weP.x += waggP[w].x; weP.y += waggP[w].y;
            weP.z += waggP[w].z; weP.w += waggP[w].w;
        }
    }

    int carO = s_carO;
    if (tid == 0 && tile == 0) {
        g_S[rowoff] = 0;
        g_Bnd[rowoff] = make_float4(0.f, 0.f, 0.f, 0.f);
    }

    int id = carO + weO + exO;
    float4 pex = make_float4(weP.x + exP.x, weP.y + exP.y,
                             weP.z + exP.z, weP.w + exP.w);
    unsigned w01 = 0, w23 = 0, w45 = 0, w67 = 0;
#pragma unroll
    for (int i = 0; i < 8; i++) {
        id += ol[i];
        unsigned u = (unsigned)id & 0xffffu;
        if (i == 0) w01 = u;        else if (i == 1) w01 |= u << 16;
        else if (i == 2) w23 = u;   else if (i == 3) w23 |= u << 16;
        else if (i == 4) w45 = u;   else if (i == 5) w45 |= u << 16;
        else if (i == 6) w67 = u;   else              w67 |= u << 16;
        if (ol[i]) {
            g_S[rowoff + id] = (int)(ebase + i - rowbase);
            g_Bnd[rowoff + id] = pex;
        }
        pex.x += pl[i].x; pex.y += pl[i].y; pex.z += pl[i].z; pex.w += pl[i].w;
    }
    *(uint4*)&g_segids[ebase] = make_uint4(w01, w23, w45, w67);

    if (tid == 255) {
        g_tP[blk] = pex;
        if (tile == NT - 1) {
            g_nOn[row] = id;
            g_S[rowoff + id + 1]   = Tn;
            g_Bnd[rowoff + id + 1] = pex;
        }
    }
}

// =====================================================================
// K3: per-segment coefficient tables (tile offsets -> global prefixes)
// =====================================================================
__global__ void __launch_bounds__(256) k_segc() {
    __shared__ float4 tOff[NT];

    pdl_wait();
    int srow = blockIdx.x;
    int ro0 = srow * SEGCAP;
    int tid = threadIdx.x, lane = tid & 31;

    if (tid < 32) {
        float4 p = g_tP[(srow << 5) + lane];
        float4 ip = p;
#pragma unroll
        for (int off = 1; off < 32; off <<= 1) {
            float a = __shfl_up_sync(~0u, ip.x, off);
            float b = __shfl_up_sync(~0u, ip.y, off);
            float c = __shfl_up_sync(~0u, ip.z, off);
            float d = __shfl_up_sync(~0u, ip.w, off);
            if (lane >= off) { ip.x += a; ip.y += b; ip.z += c; ip.w += d; }
        }
        tOff[lane] = make_float4(ip.x - p.x, ip.y - p.y, ip.z - p.z, ip.w - p.w);
    }
    __syncthreads();

    int nOn = g_nOn[srow];
    for (int s = tid; s <= nOn; s += 256) {
        int r2 = ro0 + s;
        int S0 = g_S[r2], S1 = g_S[r2 + 1];
        int t0 = S0 >> 11;
        int t1 = min(S1 >> 11, NT - 1);
        float4 O0 = tOff[t0], O1 = tOff[t1];
        float4 B0 = g_Bnd[r2], B1 = g_Bnd[r2 + 1];
        float sx = (O1.x + B1.x) - (O0.x + B0.x);
        float sy = (O1.y + B1.y) - (O0.y + B0.y);
        float sz = (O1.z + B1.z) - (O0.z + B0.z);
        float sw4 = (O1.w + B1.w) - (O0.w + B0.w);

        float invc = __fdividef(1.f, fmaxf((float)(S1 - S0), 1.f));
        float dist = 0.1f * exp2f(fast_sigmoid(sx * invc) * LOG2_20_F);
        float wmod = fast_sigmoid(sy * invc);
        float qmod = fast_sigmoid(sz * invc);
        float mu   = fast_sigmoid(sw4 * invc);

        float w = MIN_W_F * exp2f(wmod * LOG2_400_F);
        float q = 0.1f * exp2f(qmod * LOG2_20_F);
        float sh, ch;
        __sincosf(0.5f * w, &sh, &ch);
        float omc = 2.f * sh * sh;
        float cw = 1.f - omc;
        float sw = 2.f * sh * ch;
        float alpha = __fdividef(sw, 2.f * q);
        float inva0 = __fdividef(1.f, 1.f + alpha);
        float b0 = 0.5f * omc * inva0;
        float b1c = omc * inva0;
        float a1 = -2.f * cw * inva0;
        float a2 = (1.f - alpha) * inva0;

        g_segA[r2] = make_float4(-a1, -a2, b1c - a1 * b0, b0 - a2 * b0);
        g_segB[r2] = make_float2(b0, mu);
        g_segD[r2] = dist;
    }
}

// =====================================================================
// helpers
// =====================================================================
__device__ __forceinline__ void unpack_ids(uint4 sv, int ids[SPT]) {
    ids[0] = sv.x & 0xffff; ids[1] = sv.x >> 16;
    ids[2] = sv.y & 0xffff; ids[3] = sv.y >> 16;
    ids[4] = sv.z & 0xffff; ids[5] = sv.z >> 16;
    ids[6] = sv.w & 0xffff; ids[7] = sv.w >> 16;
}

__device__ __forceinline__ void compose_thread(const int ids[SPT], bool uni,
        int rowoff, float4 T0, const float xc[SPT],
        float& A00, float& A01, float& A10, float& A11, float& c1, float& c2) {
    float4 T = T0;
    A00 = 1.f; A01 = 0.f; A10 = 0.f; A11 = 1.f; c1 = 0.f; c2 = 0.f;
#pragma unroll
    for (int i = 0; i < SPT; i++) {
        if (!uni && i) T = g_segA[rowoff + ids[i]];
        float n00 = fmaf(T.x, A00, A10);
        float n01 = fmaf(T.x, A01, A11);
        float n10 = T.y * A00;
        float n11 = T.y * A01;
        float t1  = fmaf(T.z, xc[i], fmaf(T.x, c1, c2));
        float t2  = fmaf(T.w, xc[i], T.y * c1);
        A00 = n00; A01 = n01; A10 = n10; A11 = n11; c1 = t1; c2 = t2;
    }
}

// =====================================================================
// K4: stage x*dist + comb + FULL block scan; stores xc, per-thread
//     block-exclusive prefix (g_pfx*) and chunk aggregate.
// =====================================================================
__global__ void __launch_bounds__(BTH) k_scanA(const float* __restrict__ x,
                                               const float* __restrict__ f0) {
    __shared__ float sxd[SWSZ];
    __shared__ float sWex[8][6];

    int tid = threadIdx.x, blk = blockIdx.x;
    int lane = tid & 31, wid = tid >> 5;
    int base = blk * CHUNKN;
    int t0 = base & (Tn - 1);
    int rowoff = (base >> 16) * SEGCAP;
    int lbase = tid * SPT;
    int gbase = base + lbase;

    // independent prologue (overlaps k_segc tail via PDL)
    float4 f0a = *(const float4*)&f0[gbase];
    float4 f0b = *(const float4*)&f0[gbase + 4];
    float f0v[SPT] = { f0a.x, f0a.y, f0a.z, f0a.w, f0b.x, f0b.y, f0b.z, f0b.w };

    pdl_wait();

    // stage xd = x*dist over [base-LAG, base+CHUNKN)
#pragma unroll
    for (int k = tid; k < WIN / 4; k += BTH) {
        int off = k << 2;
        float4 v = make_float4(0.f, 0.f, 0.f, 0.f);
        if (t0 + off >= LAG) {
            int g = base - LAG + off;
            float4 xv = *(const float4*)&x[g];
            uint2 sv = *(const uint2*)&g_segids[g];
            int i0 = (int)(sv.x & 0xffff), i3 = (int)(sv.y >> 16);
            if (i0 == i3) {
                float d = g_segD[rowoff + i0];
                v = make_float4(xv.x * d, xv.y * d, xv.z * d, xv.w * d);
            } else {
                v.x = xv.x * g_segD[rowoff + i0];
                v.y = xv.y * g_segD[rowoff + (int)(sv.x >> 16)];
                v.z = xv.z * g_segD[rowoff + (int)(sv.y & 0xffff)];
                v.w = xv.w * g_segD[rowoff + i3];
            }
        }
        sxd[SW(off)]     = v.x;
        sxd[SW(off + 1)] = v.y;
        sxd[SW(off + 2)] = v.z;
        sxd[SW(off + 3)] = v.w;
    }
    __syncthreads();

    int ids[SPT];
    unpack_ids(*(const uint4*)&g_segids[gbase], ids);
    bool uni = (ids[0] == ids[SPT - 1]);
    float4 T = g_segA[rowoff + ids[0]];
    float2 Bc = g_segB[rowoff + ids[0]];

    float xc[SPT];
#pragma unroll
    for (int i = 0; i < SPT; i++) {
        if (!uni && i) Bc = g_segB[rowoff + ids[i]];
        float p = f0v[i] * Bc.y;
        int zi = (int)p;
        float alfa = p - (float)zi;
        int li = lbase + i + LAG;
        float x1 = sxd[SW(li - zi - 1)];
        float x2 = sxd[SW(li - zi - 2)];
        xc[i] = fmaf(alfa, x1 - x2, sxd[SW(li)] - x1);
    }
    *(float4*)&g_xc[gbase]     = make_float4(xc[0], xc[1], xc[2], xc[3]);
    *(float4*)&g_xc[gbase + 4] = make_float4(xc[4], xc[5], xc[6], xc[7]);

    float I00, I01, I10, I11, Ic1, Ic2;
    compose_thread(ids, uni, rowoff, T, xc, I00, I01, I10, I11, Ic1, Ic2);

    // warp inclusive KS
#pragma unroll
    for (int off = 1; off < 32; off <<= 1) {
        float E00 = __shfl_up_sync(~0u, I00, off);
        float E01 = __shfl_up_sync(~0u, I01, off);
        float E10 = __shfl_up_sync(~0u, I10, off);
        float E11 = __shfl_up_sync(~0u, I11, off);
        float Ec1 = __shfl_up_sync(~0u, Ic1, off);
        float Ec2 = __shfl_up_sync(~0u, Ic2, off);
        if (lane >= off) {
            float N00, N01, N10, N11, Nc1, Nc2;
            COMPOSE(E00,E01,E10,E11,Ec1,Ec2, I00,I01,I10,I11,Ic1,Ic2,
                    N00,N01,N10,N11,Nc1,Nc2);
            I00 = N00; I01 = N01; I10 = N10; I11 = N11; Ic1 = Nc1; Ic2 = Nc2;
        }
    }
    // lane-exclusive
    float X00 = __shfl_up_sync(~0u, I00, 1);
    float X01 = __shfl_up_sync(~0u, I01, 1);
    float X10 = __shfl_up_sync(~0u, I10, 1);
    float X11 = __shfl_up_sync(~0u, I11, 1);
    float Xc1 = __shfl_up_sync(~0u, Ic1, 1);
    float Xc2 = __shfl_up_sync(~0u, Ic2, 1);
    if (lane == 0) { X00 = 1.f; X01 = 0.f; X10 = 0.f; X11 = 1.f; Xc1 = 0.f; Xc2 = 0.f; }

    __shared__ float wagg[8][6];
    if (lane == 31) {
        wagg[wid][0] = I00; wagg[wid][1] = I01; wagg[wid][2] = I10;
        wagg[wid][3] = I11; wagg[wid][4] = Ic1; wagg[wid][5] = Ic2;
    }
    __syncthreads();

    // warp0: scan warp aggregates -> exclusive prefixes + block aggregate
    if (wid == 0 && lane < 8) {
        float W00 = wagg[lane][0], W01 = wagg[lane][1], W10 = wagg[lane][2];
        float W11 = wagg[lane][3], Wc1 = wagg[lane][4], Wc2 = wagg[lane][5];
#pragma unroll
        for (int off = 1; off < 8; off <<= 1) {
            float E00 = __shfl_up_sync(0xffu, W00, off);
            float E01 = __shfl_up_sync(0xffu, W01, off);
            float E10 = __shfl_up_sync(0xffu, W10, off);
            float E11 = __shfl_up_sync(0xffu, W11, off);
            float Ec1 = __shfl_up_sync(0xffu, Wc1, off);
            float Ec2 = __shfl_up_sync(0xffu, Wc2, off);
            if (lane >= off) {
                float N00, N01, N10, N11, Nc1, Nc2;
                COMPOSE(E00,E01,E10,E11,Ec1,Ec2, W00,W01,W10,W11,Wc1,Wc2,
                        N00,N01,N10,N11,Nc1,Nc2);
                W00 = N00; W01 = N01; W10 = N10; W11 = N11; Wc1 = Nc1; Wc2 = Nc2;
            }
        }
        float P00 = __shfl_up_sync(0xffu, W00, 1);
        float P01 = __shfl_up_sync(0xffu, W01, 1);
        float P10 = __shfl_up_sync(0xffu, W10, 1);
        float P11 = __shfl_up_sync(0xffu, W11, 1);
        float Pc1 = __shfl_up_sync(0xffu, Wc1, 1);
        float Pc2 = __shfl_up_sync(0xffu, Wc2, 1);
        if (lane == 0) { P00 = 1.f; P01 = 0.f; P10 = 0.f; P11 = 1.f; Pc1 = 0.f; Pc2 = 0.f; }
        sWex[lane][0] = P00; sWex[lane][1] = P01; sWex[lane][2] = P10;
        sWex[lane][3] = P11; sWex[lane][4] = Pc1; sWex[lane][5] = Pc2;
        if (lane == 7) {
            g_chunkM[blk] = make_float4(W00, W01, W10, W11);
            g_chunkC[blk] = make_float2(Wc1, Wc2);
        }
    }
    __syncthreads();

    // per-thread block-exclusive prefix = X ∘ Wex[wid]  (E=Wex, L=X)
    float E00 = sWex[wid][0], E01 = sWex[wid][1], E10 = sWex[wid][2];
    float E11 = sWex[wid][3], Ec1 = sWex[wid][4], Ec2 = sWex[wid][5];
    float P00, P01, P10, P11, Pc1, Pc2;
    COMPOSE(E00,E01,E10,E11,Ec1,Ec2, X00,X01,X10,X11,Xc1,Xc2,
            P00,P01,P10,P11,Pc1,Pc2);
    int gidx = blk * BTH + tid;
    g_pfxM[gidx] = make_float4(P00, P01, P10, P11);
    g_pfxC[gidx] = make_float2(Pc1, Pc2);
}

// =====================================================================
// K5: replay — pure elementwise + warp0 cin scan (no per-thread scans)
// =====================================================================
__global__ void __launch_bounds__(BTH) k_replay(float* __restrict__ out) {
    __shared__ float2 s_cin;

    int tid = threadIdx.x, lane = tid & 31, wid = tid >> 5;
    int blk = blockIdx.x;
    int base = blk * CHUNKN;
    int rowoff = (base >> 16) * SEGCAP;
    int gbase = base + tid * SPT;
    int gidx = blk * BTH + tid;

    pdl_wait();   // xc, prefixes, chunk aggregates complete

    float4 PM = g_pfxM[gidx];
    float2 PC = g_pfxC[gidx];
    int ids[SPT];
    unpack_ids(*(const uint4*)&g_segids[gbase], ids);
    bool uni = (ids[0] == ids[SPT - 1]);
    float4 xa = *(const float4*)&g_xc[gbase];
    float4 xb = *(const float4*)&g_xc[gbase + 4];
    float xc[SPT] = { xa.x, xa.y, xa.z, xa.w, xb.x, xb.y, xb.z, xb.w };

    // warp 0: incoming chunk state from predecessor aggregates
    if (wid == 0) {
        int chunk = blk & (NCHUNK - 1);
        int rowBlk = blk - chunk;
        float T00 = 1.f, T01 = 0.f, T10 = 0.f, T11 = 1.f, Tc1 = 0.f, Tc2 = 0.f;
        if (lane < chunk) {
            float4 M = g_chunkM[rowBlk + lane];
            float2 C = g_chunkC[rowBlk + lane];
            T00 = M.x; T01 = M.y; T10 = M.z; T11 = M.w; Tc1 = C.x; Tc2 = C.y;
        }
#pragma unroll
        for (int off = 1; off < 32; off <<= 1) {
            float E00 = __shfl_up_sync(~0u, T00, off);
            float E01 = __shfl_up_sync(~0u, T01, off);
            float E10 = __shfl_up_sync(~0u, T10, off);
            float E11 = __shfl_up_sync(~0u, T11, off);
            float Ec1 = __shfl_up_sync(~0u, Tc1, off);
            float Ec2 = __shfl_up_sync(~0u, Tc2, off);
            if (lane >= off) {
                float N00, N01, N10, N11, Nc1, Nc2;
                COMPOSE(E00,E01,E10,E11,Ec1,Ec2, T00,T01,T10,T11,Tc1,Tc2,
                        N00,N01,N10,N11,Nc1,Nc2);
                T00 = N00; T01 = N01; T10 = N10; T11 = N11; Tc1 = Nc1; Tc2 = Nc2;
            }
        }
        float i1 = 0.f, i2 = 0.f;
        if (chunk > 0) {
            i1 = __shfl_sync(~0u, Tc1, chunk - 1);
            i2 = __shfl_sync(~0u, Tc2, chunk - 1);
        }
        if (lane == 0) s_cin = make_float2(i1, i2);
    }
    __syncthreads();

    float2 cin = s_cin;
    float st1 = fmaf(PM.x, cin.x, fmaf(PM.y, cin.y, PC.x));
    float st2 = fmaf(PM.z, cin.x, fmaf(PM.w, cin.y, PC.y));

    float4 T = g_segA[rowoff + ids[0]];
    float2 Bc = g_segB[rowoff + ids[0]];
    float ov[SPT];
#pragma unroll
    for (int i = 0; i < SPT; i++) {
        if (!uni && i) { T = g_segA[rowoff + ids[i]]; Bc = g_segB[rowoff + ids[i]]; }
        ov[i] = fmaf(Bc.x, xc[i], st1);
        float n1 = fmaf(T.z, xc[i], fmaf(T.x, st1, st2));
        float n2 = fmaf(T.w, xc[i], T.y * st1);
        st1 = n1; st2 = n2;
    }
    *(float4*)&out[gbase]     = make_float4(ov[0], ov[1], ov[2], ov[3]);
    *(float4*)&out[gbase + 4] = make_float4(ov[4], ov[5], ov[6], ov[7]);
}

// =====================================================================
template <typename F, typename... Args>
static void launch_pdl(F fn, int grid, int block, Args... args) {
    cudaLaunchConfig_t cfg = {};
    cfg.gridDim = dim3(grid, 1, 1);
    cfg.blockDim = dim3(block, 1, 1);
    cudaLaunchAttribute attr[1];
    attr[0].id = cudaLaunchAttributeProgrammaticStreamSerialization;
    attr[0].val.programmaticStreamSerializationAllowed = 1;
    cfg.attrs = attr;
    cfg.numAttrs = 1;
    cudaLaunchKernelEx(&cfg, fn, args...);
}

extern "C" void kernel_launch(void* const* d_in, const int* in_sizes, int n_in,
                              void* d_out, int out_size) {
    const float* f0     = (const float*)d_in[0];
    const float* x      = (const float*)d_in[1];
    const float* params = (const float*)d_in[2];
    const int*   onsets = (const int*)d_in[3];
    float* out = (float*)d_out;

    k_tile<<<Bn * NT, 256>>>((const int4*)onsets);
    launch_pdl(k_ids,    Bn * NT,     256, (const int4*)onsets, (const float4*)params);
    launch_pdl(k_segc,   Bn,          256);
    launch_pdl(k_scanA,  Bn * NCHUNK, BTH, x, f0);
    launch_pdl(k_replay, Bn * NCHUNK, BTH, out);
}